// round 3
// baseline (speedup 1.0000x reference)
#include <cuda_runtime.h>

#define NN  50000
#define NE  800000
#define DIN 128
#define DH  256
#define NP  512
#define NC  16

// ---------------- device scratch (no allocations allowed) ----------------
__device__ float g_deg[NN];
__device__ float g_dis[NN];
__device__ int   g_row_off[NN + 1];
__device__ int   g_fill[NN];
__device__ int   g_csr_src[NE];
__device__ float g_csr_w[NE];
__device__ __align__(16) float g_M [(size_t)NN * DH];   // messages (h @ W)
__device__ __align__(16) float g_H1[(size_t)NN * DH];   // layer-1 pre-relu
__device__ __align__(16) float g_H2[(size_t)NN * DH];   // layer-2 out -> normalized hn
__device__ __align__(16) float g_anch [NP * DH];        // anchors (normalized)
__device__ __align__(16) float g_anchT[DH * NP];        // anchors transposed [k][p]
__device__ __align__(16) float g_T1[NP * DH];           // anchors @ Wl1 + bl1 (pre-relu)
__device__ float g_outproto[NP * NC];
__device__ int   g_not64;

// ---------------- setup kernels ----------------
__global__ void init_kernel() {
    int i = blockIdx.x * blockDim.x + threadIdx.x;
    if (i == 0) g_not64 = 0;
    if (i < NN) g_deg[i] = 1.0f;            // self-loop
}

// int64 vs int32 probe: int64 nonneg values < 2^31 have all-zero high words
__global__ void detect_kernel(const unsigned* __restrict__ ei32) {
    int t = blockIdx.x * blockDim.x + threadIdx.x;
    if (t < 1024) { if (ei32[2 * t + 1] != 0u) atomicOr(&g_not64, 1); }
}

__global__ void count_kernel(const void* __restrict__ ei) {
    int e = blockIdx.x * blockDim.x + threadIdx.x;
    if (e >= NE) return;
    int is64 = (g_not64 == 0);
    int dst = is64 ? (int)((const long long*)ei)[NE + e] : ((const int*)ei)[NE + e];
    atomicAdd(&g_deg[dst], 1.0f);
}

__global__ void dis_kernel() {
    int i = blockIdx.x * blockDim.x + threadIdx.x;
    if (i < NN) g_dis[i] = rsqrtf(g_deg[i]);
}

// single-block exclusive scan of per-dst edge counts (deg-1) -> row_off, fill
__global__ void scan_kernel() {
    __shared__ int sm[1024];
    __shared__ int carry;
    int tid = threadIdx.x;
    if (tid == 0) { carry = 0; g_row_off[0] = 0; }
    __syncthreads();
    for (int base = 0; base < NN; base += 1024) {
        int i = base + tid;
        int v = (i < NN) ? ((int)g_deg[i]) - 1 : 0;
        sm[tid] = v; __syncthreads();
        for (int off = 1; off < 1024; off <<= 1) {
            int t = (tid >= off) ? sm[tid - off] : 0;
            __syncthreads();
            sm[tid] += t;
            __syncthreads();
        }
        int inc = sm[tid] + carry;
        if (i < NN) { g_row_off[i + 1] = inc; g_fill[i] = inc - v; }
        __syncthreads();
        if (tid == 1023) carry = inc;
        __syncthreads();
    }
}

__global__ void fill_kernel(const void* __restrict__ ei) {
    int e = blockIdx.x * blockDim.x + threadIdx.x;
    if (e >= NE) return;
    int is64 = (g_not64 == 0);
    int src, dst;
    if (is64) {
        src = (int)((const long long*)ei)[e];
        dst = (int)((const long long*)ei)[NE + e];
    } else {
        src = ((const int*)ei)[e];
        dst = ((const int*)ei)[NE + e];
    }
    int pos = atomicAdd(&g_fill[dst], 1);
    g_csr_src[pos] = src;
    g_csr_w[pos]   = g_dis[src] * g_dis[dst];
}

// ---------------- fp32x2 GEMM: out[r][c] = sum_k A[r][k]*W[k][c] (+bias) ----------------
// blockDim.x == NCOL, one column per thread, TM rows per block.
// A tile stored transposed so row pairs are contiguous -> one LDS.64 feeds one fma.rn.f32x2.
template<int NCOL, int TM, int KT, bool RELU_IN>
__global__ void __launch_bounds__(NCOL)
gemm_kernel(const float* __restrict__ A, const float* __restrict__ W,
            const float* __restrict__ bias, float* __restrict__ out,
            int nrows, int K)
{
    constexpr int ATS = TM + 2;  // pad: even stride (8B align), reduced store conflicts
    __shared__ __align__(16) float Ws [KT * NCOL];
    __shared__ __align__(16) float AsT[KT * ATS];
    const int tid  = threadIdx.x;
    const int row0 = blockIdx.x * TM;

    unsigned long long acc2[TM / 2];
#pragma unroll
    for (int r = 0; r < TM / 2; r++) acc2[r] = 0ull;

    for (int kc = 0; kc < K; kc += KT) {
#pragma unroll
        for (int j = 0; j < KT; j++)
            Ws[j * NCOL + tid] = W[(size_t)(kc + j) * NCOL + tid];
#pragma unroll
        for (int idx = tid; idx < TM * KT; idx += NCOL) {
            int k = idx % KT, r = idx / KT;
            int rg = row0 + r; if (rg >= nrows) rg = nrows - 1;
            float v = A[(size_t)rg * K + kc + k];
            if (RELU_IN) v = fmaxf(v, 0.0f);
            AsT[k * ATS + r] = v;
        }
        __syncthreads();
#pragma unroll 4
        for (int k = 0; k < KT; k++) {
            float w = Ws[k * NCOL + tid];
            unsigned long long w2;
            asm("mov.b64 %0, {%1, %1};" : "=l"(w2) : "f"(w));
            const unsigned long long* ap =
                reinterpret_cast<const unsigned long long*>(&AsT[k * ATS]);
#pragma unroll
            for (int r = 0; r < TM / 2; r++) {
                unsigned long long a2 = ap[r];
                asm("fma.rn.f32x2 %0, %1, %2, %0;" : "+l"(acc2[r]) : "l"(a2), "l"(w2));
            }
        }
        __syncthreads();
    }
    float bv = (bias != nullptr) ? bias[tid] : 0.0f;
#pragma unroll
    for (int r = 0; r < TM / 2; r++) {
        float lo = __uint_as_float((unsigned)(acc2[r] & 0xffffffffull));
        float hi = __uint_as_float((unsigned)(acc2[r] >> 32));
        int r0 = row0 + 2 * r;
        if (r0 < nrows)     out[(size_t)r0 * NCOL + tid]       = lo + bv;
        if (r0 + 1 < nrows) out[(size_t)(r0 + 1) * NCOL + tid] = hi + bv;
    }
}

// ---------------- CSR gather-aggregate: H[i] = b + dis[i]^2*M[i] + sum_e w_e*M[src_e] ----------------
__global__ void agg_kernel(const float* __restrict__ Msg,
                           const float* __restrict__ bias,
                           float* __restrict__ Hout)
{
    int wid = threadIdx.x >> 5, lane = threadIdx.x & 31;
    int i = blockIdx.x * 8 + wid;
    if (i >= NN) return;
    int cb = lane * 8;
    const float4* bp = (const float4*)(bias + cb);
    float4 b0 = bp[0], b1 = bp[1];
    float d  = g_dis[i];
    float sw = d * d;                       // self-loop weight
    const float4* mr = (const float4*)(Msg + (size_t)i * DH + cb);
    float4 m0 = mr[0], m1 = mr[1];
    float a0 = b0.x + sw * m0.x, a1 = b0.y + sw * m0.y;
    float a2 = b0.z + sw * m0.z, a3 = b0.w + sw * m0.w;
    float a4 = b1.x + sw * m1.x, a5 = b1.y + sw * m1.y;
    float a6 = b1.z + sw * m1.z, a7 = b1.w + sw * m1.w;

    int beg = g_row_off[i], end = g_row_off[i + 1];
    for (int j0 = beg; j0 < end; j0 += 32) {
        int jj = j0 + lane;
        int s = 0; float w = 0.f;
        if (jj < end) { s = g_csr_src[jj]; w = g_csr_w[jj]; }
        int cnt = min(32, end - j0);
        for (int t = 0; t < cnt; t++) {
            int   src = __shfl_sync(0xffffffffu, s, t);
            float ww  = __shfl_sync(0xffffffffu, w, t);
            const float4* sr = (const float4*)(Msg + (size_t)src * DH + cb);
            float4 v0 = sr[0], v1 = sr[1];
            a0 += ww * v0.x; a1 += ww * v0.y; a2 += ww * v0.z; a3 += ww * v0.w;
            a4 += ww * v1.x; a5 += ww * v1.y; a6 += ww * v1.z; a7 += ww * v1.w;
        }
    }
    float4* op = (float4*)(Hout + (size_t)i * DH + cb);
    op[0] = make_float4(a0, a1, a2, a3);
    op[1] = make_float4(a4, a5, a6, a7);
}

// ---------------- L2 row-normalize in place (warp per row) ----------------
__global__ void norm_kernel(float* __restrict__ H) {
    int wid = threadIdx.x >> 5, lane = threadIdx.x & 31;
    int i = blockIdx.x * 8 + wid;
    if (i >= NN) return;
    float4* p = (float4*)(H + (size_t)i * DH + lane * 8);
    float4 v0 = p[0], v1 = p[1];
    float ss = v0.x * v0.x + v0.y * v0.y + v0.z * v0.z + v0.w * v0.w
             + v1.x * v1.x + v1.y * v1.y + v1.z * v1.z + v1.w * v1.w;
#pragma unroll
    for (int off = 16; off; off >>= 1) ss += __shfl_xor_sync(0xffffffffu, ss, off);
    float rinv = rsqrtf(ss);
    v0.x *= rinv; v0.y *= rinv; v0.z *= rinv; v0.w *= rinv;
    v1.x *= rinv; v1.y *= rinv; v1.z *= rinv; v1.w *= rinv;
    p[0] = v0; p[1] = v1;
}

// ---------------- anchor gather (normalized rows) + transposed copy ----------------
__global__ void gather_kernel(const void* __restrict__ prot,
                              const float* __restrict__ H,
                              float* __restrict__ anch,
                              float* __restrict__ anchT)
{
    int idx = blockIdx.x * blockDim.x + threadIdx.x;
    if (idx >= NP * DH) return;
    int p = idx >> 8, k = idx & 255;
    int is64 = (g_not64 == 0);
    long long node = is64 ? ((const long long*)prot)[p]
                          : (long long)((const int*)prot)[p];
    float v = H[(size_t)node * DH + k];
    anch[idx] = v;
    anchT[(size_t)k * NP + p] = v;
}

// ---------------- prototype head: log_softmax(relu(T1) @ Wl2 + bl2) ----------------
__global__ void proto_head_kernel(const float* __restrict__ T1,
                                  const float* __restrict__ Wl2,
                                  const float* __restrict__ bl2,
                                  float* __restrict__ out_g,
                                  float* __restrict__ out_s)
{
    __shared__ float sm[8][NC];
    __shared__ float zz[NC];
    int p = blockIdx.x;
    int tid = threadIdx.x;
    float t = fmaxf(T1[p * DH + tid], 0.0f);
    float part[NC];
#pragma unroll
    for (int c = 0; c < NC; c++) part[c] = t * Wl2[tid * NC + c];
#pragma unroll
    for (int off = 16; off; off >>= 1)
#pragma unroll
        for (int c = 0; c < NC; c++)
            part[c] += __shfl_xor_sync(0xffffffffu, part[c], off);
    int wid = tid >> 5, lane = tid & 31;
    if (lane == 0)
#pragma unroll
        for (int c = 0; c < NC; c++) sm[wid][c] = part[c];
    __syncthreads();
    if (tid < NC) {
        float z = bl2[tid];
#pragma unroll
        for (int w = 0; w < 8; w++) z += sm[w][tid];
        zz[tid] = z;
        __syncwarp(0x0000ffffu);
        float m = -1e30f;
#pragma unroll
        for (int c = 0; c < NC; c++) m = fmaxf(m, zz[c]);
        float s = 0.f;
#pragma unroll
        for (int c = 0; c < NC; c++) s += expf(zz[c] - m);
        float val = z - m - logf(s);
        out_g[p * NC + tid] = val;
        out_s[p * NC + tid] = val;
    }
}

// ---------------- out = log_softmax(x_rel @ out_proto), warp per node row ----------------
__global__ void out_kernel(const float* __restrict__ xrel,
                           const float* __restrict__ outproto,
                           float* __restrict__ out)
{
    __shared__ float ops[NP * 17];   // padded stride -> no bank conflicts
    for (int idx = threadIdx.x; idx < NP * NC; idx += blockDim.x) {
        int p = idx >> 4, c = idx & 15;
        ops[p * 17 + c] = outproto[idx];
    }
    __syncthreads();
    int wid = threadIdx.x >> 5, lane = threadIdx.x & 31;
    int i = blockIdx.x * 8 + wid;
    if (i >= NN) return;
    float acc[NC];
#pragma unroll
    for (int c = 0; c < NC; c++) acc[c] = 0.f;
    const float* xr = xrel + (size_t)i * NP;
#pragma unroll
    for (int j = 0; j < NP / 32; j++) {
        int p = lane + j * 32;
        float xv = xr[p];
        const float* o = &ops[p * 17];
#pragma unroll
        for (int c = 0; c < NC; c++) acc[c] += xv * o[c];
    }
#pragma unroll
    for (int off = 16; off; off >>= 1)
#pragma unroll
        for (int c = 0; c < NC; c++)
            acc[c] += __shfl_xor_sync(0xffffffffu, acc[c], off);
    float m = -1e30f;
#pragma unroll
    for (int c = 0; c < NC; c++) m = fmaxf(m, acc[c]);
    float s = 0.f;
#pragma unroll
    for (int c = 0; c < NC; c++) s += expf(acc[c] - m);
    float l = m + logf(s);
    if (lane < NC) out[(size_t)i * NC + lane] = acc[lane] - l;
}

// ---------------- launch ----------------
extern "C" void kernel_launch(void* const* d_in, const int* in_sizes, int n_in,
                              void* d_out, int out_size)
{
    const float* x    = (const float*)d_in[0];
    const void*  ei   = d_in[1];
    const void*  prot = d_in[2];

    // locate W0 by size (epoch scalar may or may not be materialized as an input)
    int wi = 3;
    while (wi < n_in && in_sizes[wi] != DIN * DH) wi++;
    const float* W0  = (const float*)d_in[wi + 0];
    const float* b0  = (const float*)d_in[wi + 1];
    const float* W1  = (const float*)d_in[wi + 2];
    const float* b1  = (const float*)d_in[wi + 3];
    const float* Wl1 = (const float*)d_in[wi + 4];
    const float* bl1 = (const float*)d_in[wi + 5];
    const float* Wl2 = (const float*)d_in[wi + 6];
    const float* bl2 = (const float*)d_in[wi + 7];

    float* out   = (float*)d_out;                              // [NN, NC]
    float* xrel  = out + (size_t)NN * NC;                      // [NN, NP]
    float* outpr = out + (size_t)NN * NC + (size_t)NN * NP;    // [NP, NC]

    float *pM, *pH1, *pH2, *pAnch, *pAnchT, *pT1, *pOutp;
    cudaGetSymbolAddress((void**)&pM,     g_M);
    cudaGetSymbolAddress((void**)&pH1,    g_H1);
    cudaGetSymbolAddress((void**)&pH2,    g_H2);
    cudaGetSymbolAddress((void**)&pAnch,  g_anch);
    cudaGetSymbolAddress((void**)&pAnchT, g_anchT);
    cudaGetSymbolAddress((void**)&pT1,    g_T1);
    cudaGetSymbolAddress((void**)&pOutp,  g_outproto);

    // graph preprocessing
    init_kernel  <<<(NN + 255) / 256, 256>>>();
    detect_kernel<<<4, 256>>>((const unsigned*)ei);
    count_kernel <<<(NE + 255) / 256, 256>>>(ei);
    dis_kernel   <<<(NN + 255) / 256, 256>>>();
    scan_kernel  <<<1, 1024>>>();
    fill_kernel  <<<(NE + 255) / 256, 256>>>(ei);

    // layer 0: M = x @ W0 ; H1 = agg(M) + b0
    gemm_kernel<DH, 32, 32, false><<<(NN + 31) / 32, DH>>>(x, W0, nullptr, pM, NN, DIN);
    agg_kernel<<<(NN + 7) / 8, 256>>>(pM, b0, pH1);

    // layer 1: M = relu(H1) @ W1 ; H2 = agg(M) + b1
    gemm_kernel<DH, 32, 32, true><<<(NN + 31) / 32, DH>>>(pH1, W1, nullptr, pM, NN, DH);
    agg_kernel<<<(NN + 7) / 8, 256>>>(pM, b1, pH2);

    // normalize rows -> hn (in place)
    norm_kernel<<<(NN + 7) / 8, 256>>>(pH2);

    // anchors + prototype head
    gather_kernel<<<(NP * DH + 255) / 256, 256>>>(prot, pH2, pAnch, pAnchT);
    gemm_kernel<DH, 32, 32, false><<<NP / 32, DH>>>(pAnch, Wl1, bl1, pT1, NP, DH);
    proto_head_kernel<<<NP, 256>>>(pT1, Wl2, bl2, outpr, pOutp);

    // x_rel = hn @ anchors^T  (cosine sim of unit rows)
    gemm_kernel<512, 32, 16, false><<<(NN + 31) / 32, 512>>>(pH2, pAnchT, nullptr, xrel, NN, DH);

    // out = log_softmax(x_rel @ out_proto)
    out_kernel<<<(NN + 7) / 8, 256>>>(xrel, pOutp, out);

    (void)out_size; (void)in_sizes; (void)n_in;
}

// round 5
// speedup vs baseline: 1.6256x; 1.6256x over previous
#include <cuda_runtime.h>

#define NN  50000
#define NE  800000
#define DIN 128
#define DH  256
#define NP  512
#define NC  16

// ---------------- device scratch (no allocations allowed) ----------------
__device__ float g_deg[NN];
__device__ float g_dis[NN];
__device__ int   g_row_off[NN + 1];
__device__ int   g_fill[NN];
__device__ int   g_csr_src[NE];
__device__ float g_csr_w[NE];
__device__ __align__(16) float g_M [(size_t)NN * DH];   // aggregated features
__device__ __align__(16) float g_H1[(size_t)NN * DH];   // layer-0 output (pre-relu)
__device__ __align__(16) float g_H2[(size_t)NN * DH];   // layer-1 output -> normalized
__device__ __align__(16) float g_anch [NP * DH];        // anchors (normalized)
__device__ __align__(16) float g_anchT[DH * NP];        // anchors transposed [k][p]
__device__ __align__(16) float g_T1[NP * DH];           // anchors @ Wl1 + bl1 (pre-relu)
__device__ float g_outproto[NP * NC];
__device__ int   g_not64;

// ---------------- setup kernels ----------------
__global__ void init_kernel() {
    int i = blockIdx.x * blockDim.x + threadIdx.x;
    if (i == 0) g_not64 = 0;
    if (i < NN) g_deg[i] = 1.0f;            // self-loop
}

// int64 vs int32 probe: int64 nonneg values < 2^31 have all-zero high words
__global__ void detect_kernel(const unsigned* __restrict__ ei32) {
    int t = blockIdx.x * blockDim.x + threadIdx.x;
    if (t < 1024) { if (ei32[2 * t + 1] != 0u) atomicOr(&g_not64, 1); }
}

__global__ void count_kernel(const void* __restrict__ ei) {
    int e = blockIdx.x * blockDim.x + threadIdx.x;
    if (e >= NE) return;
    int is64 = (g_not64 == 0);
    int dst = is64 ? (int)((const long long*)ei)[NE + e] : ((const int*)ei)[NE + e];
    atomicAdd(&g_deg[dst], 1.0f);
}

__global__ void dis_kernel() {
    int i = blockIdx.x * blockDim.x + threadIdx.x;
    if (i < NN) g_dis[i] = rsqrtf(g_deg[i]);
}

// single-block exclusive scan of per-dst edge counts (deg-1) -> row_off, fill
__global__ void scan_kernel() {
    __shared__ int sm[1024];
    __shared__ int carry;
    int tid = threadIdx.x;
    if (tid == 0) { carry = 0; g_row_off[0] = 0; }
    __syncthreads();
    for (int base = 0; base < NN; base += 1024) {
        int i = base + tid;
        int v = (i < NN) ? ((int)g_deg[i]) - 1 : 0;
        sm[tid] = v; __syncthreads();
        for (int off = 1; off < 1024; off <<= 1) {
            int t = (tid >= off) ? sm[tid - off] : 0;
            __syncthreads();
            sm[tid] += t;
            __syncthreads();
        }
        int inc = sm[tid] + carry;
        if (i < NN) { g_row_off[i + 1] = inc; g_fill[i] = inc - v; }
        __syncthreads();
        if (tid == 1023) carry = inc;
        __syncthreads();
    }
}

__global__ void fill_kernel(const void* __restrict__ ei) {
    int e = blockIdx.x * blockDim.x + threadIdx.x;
    if (e >= NE) return;
    int is64 = (g_not64 == 0);
    int src, dst;
    if (is64) {
        src = (int)((const long long*)ei)[e];
        dst = (int)((const long long*)ei)[NE + e];
    } else {
        src = ((const int*)ei)[e];
        dst = ((const int*)ei)[NE + e];
    }
    int pos = atomicAdd(&g_fill[dst], 1);
    g_csr_src[pos] = src;
    g_csr_w[pos]   = g_dis[src] * g_dis[dst];
}

// ---------------- register-blocked fp32x2 GEMM ----------------
// C[r][n] = sum_k A[r][k] * B[k][n] (+ bias[n])
// 64x64 block tile, 128 threads, 8x4 thread tile, BK=16.
// A tile stored transposed so row-pairs feed fma.rn.f32x2 via one LDS.64.
template<bool BIAS>
__global__ void __launch_bounds__(128)
gemm64_kernel(const float* __restrict__ A, const float* __restrict__ B,
              const float* __restrict__ bias, float* __restrict__ C,
              int nrows, int K, int N)
{
    __shared__ __align__(16) float AsT[16][66];   // [k][row], 8B-aligned rows
    __shared__ __align__(16) float Bs [16][68];   // [k][col], 16B-aligned rows

    const int tid  = threadIdx.x;
    const int row0 = blockIdx.x * 64;
    const int n0   = blockIdx.y * 64;
    const int tc   = (tid & 15) * 4;   // 4 contiguous columns
    const int tr   = (tid >> 4) * 8;   // 8 contiguous rows (4 pairs)

    unsigned long long acc2[4][4];     // [col][row-pair]
#pragma unroll
    for (int c = 0; c < 4; c++)
#pragma unroll
        for (int p = 0; p < 4; p++) acc2[c][p] = 0ull;

    for (int kc = 0; kc < K; kc += 16) {
        // A tile: 64 rows x 16 k, 256 float4 loads
#pragma unroll
        for (int i = 0; i < 2; i++) {
            int idx = tid + i * 128;
            int r = idx >> 2, kq = idx & 3;
            int rg = row0 + r;
            float4 v = make_float4(0.f, 0.f, 0.f, 0.f);
            if (rg < nrows)
                v = *(const float4*)&A[(size_t)rg * K + kc + kq * 4];
            AsT[kq * 4 + 0][r] = v.x;
            AsT[kq * 4 + 1][r] = v.y;
            AsT[kq * 4 + 2][r] = v.z;
            AsT[kq * 4 + 3][r] = v.w;
        }
        // B tile: 16 k x 64 cols
#pragma unroll
        for (int i = 0; i < 2; i++) {
            int idx = tid + i * 128;
            int k = idx >> 4, nq = idx & 15;
            *(float4*)&Bs[k][nq * 4] =
                *(const float4*)&B[(size_t)(kc + k) * N + n0 + nq * 4];
        }
        __syncthreads();

#pragma unroll
        for (int k = 0; k < 16; k++) {
            unsigned long long a2[4];
#pragma unroll
            for (int p = 0; p < 4; p++)
                a2[p] = *(const unsigned long long*)&AsT[k][tr + 2 * p];
            float4 b = *(const float4*)&Bs[k][tc];
            unsigned long long w2[4];
            asm("mov.b64 %0, {%1, %1};" : "=l"(w2[0]) : "f"(b.x));
            asm("mov.b64 %0, {%1, %1};" : "=l"(w2[1]) : "f"(b.y));
            asm("mov.b64 %0, {%1, %1};" : "=l"(w2[2]) : "f"(b.z));
            asm("mov.b64 %0, {%1, %1};" : "=l"(w2[3]) : "f"(b.w));
#pragma unroll
            for (int c = 0; c < 4; c++)
#pragma unroll
                for (int p = 0; p < 4; p++)
                    asm("fma.rn.f32x2 %0, %1, %2, %0;"
                        : "+l"(acc2[c][p]) : "l"(a2[p]), "l"(w2[c]));
        }
        __syncthreads();
    }

    float4 bv = make_float4(0.f, 0.f, 0.f, 0.f);
    if (BIAS) bv = *(const float4*)&bias[n0 + tc];
#pragma unroll
    for (int p = 0; p < 4; p++) {
        int rlo = row0 + tr + 2 * p;
        float4 lo, hi;
        lo.x = __uint_as_float((unsigned)(acc2[0][p] & 0xffffffffull)) + bv.x;
        lo.y = __uint_as_float((unsigned)(acc2[1][p] & 0xffffffffull)) + bv.y;
        lo.z = __uint_as_float((unsigned)(acc2[2][p] & 0xffffffffull)) + bv.z;
        lo.w = __uint_as_float((unsigned)(acc2[3][p] & 0xffffffffull)) + bv.w;
        hi.x = __uint_as_float((unsigned)(acc2[0][p] >> 32)) + bv.x;
        hi.y = __uint_as_float((unsigned)(acc2[1][p] >> 32)) + bv.y;
        hi.z = __uint_as_float((unsigned)(acc2[2][p] >> 32)) + bv.z;
        hi.w = __uint_as_float((unsigned)(acc2[3][p] >> 32)) + bv.w;
        if (rlo < nrows)     *(float4*)&C[(size_t)rlo * N + n0 + tc]       = lo;
        if (rlo + 1 < nrows) *(float4*)&C[(size_t)(rlo + 1) * N + n0 + tc] = hi;
    }
}

// ---------------- CSR gather-aggregate ----------------
// H[i] = dis[i]^2 * f(M[i]) + sum_e w_e * f(M[src_e]),  f = relu or identity
template<int D, bool RELU>
__global__ void agg_kernel(const float* __restrict__ Msg, float* __restrict__ Hout)
{
    constexpr int V = D / 128;          // float4s per lane (1 or 2)
    int wid = threadIdx.x >> 5, lane = threadIdx.x & 31;
    int i = blockIdx.x * 8 + wid;
    if (i >= NN) return;
    int cb = lane * 4 * V;

    float d  = g_dis[i];
    float sw = d * d;                   // self-loop weight
    float4 acc[V];
    const float4* mr = (const float4*)(Msg + (size_t)i * D + cb);
#pragma unroll
    for (int v = 0; v < V; v++) {
        float4 m = mr[v];
        if (RELU) { m.x = fmaxf(m.x, 0.f); m.y = fmaxf(m.y, 0.f);
                    m.z = fmaxf(m.z, 0.f); m.w = fmaxf(m.w, 0.f); }
        acc[v] = make_float4(sw * m.x, sw * m.y, sw * m.z, sw * m.w);
    }

    int beg = g_row_off[i], end = g_row_off[i + 1];
    for (int j0 = beg; j0 < end; j0 += 32) {
        int jj = j0 + lane;
        int s = 0; float w = 0.f;
        if (jj < end) { s = g_csr_src[jj]; w = g_csr_w[jj]; }
        int cnt = min(32, end - j0);
        for (int t = 0; t < cnt; t++) {
            int   src = __shfl_sync(0xffffffffu, s, t);
            float ww  = __shfl_sync(0xffffffffu, w, t);
            const float4* sr = (const float4*)(Msg + (size_t)src * D + cb);
#pragma unroll
            for (int v = 0; v < V; v++) {
                float4 m = sr[v];
                if (RELU) { m.x = fmaxf(m.x, 0.f); m.y = fmaxf(m.y, 0.f);
                            m.z = fmaxf(m.z, 0.f); m.w = fmaxf(m.w, 0.f); }
                acc[v].x += ww * m.x; acc[v].y += ww * m.y;
                acc[v].z += ww * m.z; acc[v].w += ww * m.w;
            }
        }
    }
    float4* op = (float4*)(Hout + (size_t)i * D + cb);
#pragma unroll
    for (int v = 0; v < V; v++) op[v] = acc[v];
}

// ---------------- L2 row-normalize in place (warp per row) ----------------
__global__ void norm_kernel(float* __restrict__ H) {
    int wid = threadIdx.x >> 5, lane = threadIdx.x & 31;
    int i = blockIdx.x * 8 + wid;
    if (i >= NN) return;
    float4* p = (float4*)(H + (size_t)i * DH + lane * 8);
    float4 v0 = p[0], v1 = p[1];
    float ss = v0.x * v0.x + v0.y * v0.y + v0.z * v0.z + v0.w * v0.w
             + v1.x * v1.x + v1.y * v1.y + v1.z * v1.z + v1.w * v1.w;
#pragma unroll
    for (int off = 16; off; off >>= 1) ss += __shfl_xor_sync(0xffffffffu, ss, off);
    float rinv = rsqrtf(ss);
    v0.x *= rinv; v0.y *= rinv; v0.z *= rinv; v0.w *= rinv;
    v1.x *= rinv; v1.y *= rinv; v1.z *= rinv; v1.w *= rinv;
    p[0] = v0; p[1] = v1;
}

// ---------------- anchor gather (normalized rows) + transposed copy ----------------
__global__ void gather_kernel(const void* __restrict__ prot,
                              const float* __restrict__ H,
                              float* __restrict__ anch,
                              float* __restrict__ anchT)
{
    int idx = blockIdx.x * blockDim.x + threadIdx.x;
    if (idx >= NP * DH) return;
    int p = idx >> 8, k = idx & 255;
    int is64 = (g_not64 == 0);
    long long node = is64 ? ((const long long*)prot)[p]
                          : (long long)((const int*)prot)[p];
    float v = H[(size_t)node * DH + k];
    anch[idx] = v;
    anchT[(size_t)k * NP + p] = v;
}

// ---------------- prototype head: log_softmax(relu(T1) @ Wl2 + bl2) ----------------
__global__ void proto_head_kernel(const float* __restrict__ T1,
                                  const float* __restrict__ Wl2,
                                  const float* __restrict__ bl2,
                                  float* __restrict__ out_g,
                                  float* __restrict__ out_s)
{
    __shared__ float sm[8][NC];
    __shared__ float zz[NC];
    int p = blockIdx.x;
    int tid = threadIdx.x;
    float t = fmaxf(T1[p * DH + tid], 0.0f);
    float part[NC];
#pragma unroll
    for (int c = 0; c < NC; c++) part[c] = t * Wl2[tid * NC + c];
#pragma unroll
    for (int off = 16; off; off >>= 1)
#pragma unroll
        for (int c = 0; c < NC; c++)
            part[c] += __shfl_xor_sync(0xffffffffu, part[c], off);
    int wid = tid >> 5, lane = tid & 31;
    if (lane == 0)
#pragma unroll
        for (int c = 0; c < NC; c++) sm[wid][c] = part[c];
    __syncthreads();
    if (tid < NC) {
        float z = bl2[tid];
#pragma unroll
        for (int w = 0; w < 8; w++) z += sm[w][tid];
        zz[tid] = z;
        __syncwarp(0x0000ffffu);
        float m = -1e30f;
#pragma unroll
        for (int c = 0; c < NC; c++) m = fmaxf(m, zz[c]);
        float s = 0.f;
#pragma unroll
        for (int c = 0; c < NC; c++) s += expf(zz[c] - m);
        float val = z - m - logf(s);
        out_g[p * NC + tid] = val;
        out_s[p * NC + tid] = val;
    }
}

// ---------------- out = log_softmax(x_rel @ out_proto), warp per node row ----------------
__global__ void out_kernel(const float* __restrict__ xrel,
                           const float* __restrict__ outproto,
                           float* __restrict__ out)
{
    __shared__ float ops[NP * 17];   // padded stride -> no bank conflicts
    for (int idx = threadIdx.x; idx < NP * NC; idx += blockDim.x) {
        int p = idx >> 4, c = idx & 15;
        ops[p * 17 + c] = outproto[idx];
    }
    __syncthreads();
    int wid = threadIdx.x >> 5, lane = threadIdx.x & 31;
    int i = blockIdx.x * 8 + wid;
    if (i >= NN) return;
    float acc[NC];
#pragma unroll
    for (int c = 0; c < NC; c++) acc[c] = 0.f;
    const float* xr = xrel + (size_t)i * NP;
#pragma unroll
    for (int j = 0; j < NP / 32; j++) {
        int p = lane + j * 32;
        float xv = xr[p];
        const float* o = &ops[p * 17];
#pragma unroll
        for (int c = 0; c < NC; c++) acc[c] += xv * o[c];
    }
#pragma unroll
    for (int off = 16; off; off >>= 1)
#pragma unroll
        for (int c = 0; c < NC; c++)
            acc[c] += __shfl_xor_sync(0xffffffffu, acc[c], off);
    float m = -1e30f;
#pragma unroll
    for (int c = 0; c < NC; c++) m = fmaxf(m, acc[c]);
    float s = 0.f;
#pragma unroll
    for (int c = 0; c < NC; c++) s += expf(acc[c] - m);
    float l = m + logf(s);
    if (lane < NC) out[(size_t)i * NC + lane] = acc[lane] - l;
}

// ---------------- launch ----------------
extern "C" void kernel_launch(void* const* d_in, const int* in_sizes, int n_in,
                              void* d_out, int out_size)
{
    const float* x    = (const float*)d_in[0];
    const void*  ei   = d_in[1];
    const void*  prot = d_in[2];

    // locate W0 by size (epoch scalar may or may not be materialized as an input)
    int wi = 3;
    while (wi < n_in && in_sizes[wi] != DIN * DH) wi++;
    const float* W0  = (const float*)d_in[wi + 0];
    const float* b0  = (const float*)d_in[wi + 1];
    const float* W1  = (const float*)d_in[wi + 2];
    const float* b1  = (const float*)d_in[wi + 3];
    const float* Wl1 = (const float*)d_in[wi + 4];
    const float* bl1 = (const float*)d_in[wi + 5];
    const float* Wl2 = (const float*)d_in[wi + 6];
    const float* bl2 = (const float*)d_in[wi + 7];

    float* out   = (float*)d_out;                              // [NN, NC]
    float* xrel  = out + (size_t)NN * NC;                      // [NN, NP]
    float* outpr = out + (size_t)NN * NC + (size_t)NN * NP;    // [NP, NC]

    float *pM, *pH1, *pH2, *pAnch, *pAnchT, *pT1, *pOutp;
    cudaGetSymbolAddress((void**)&pM,     g_M);
    cudaGetSymbolAddress((void**)&pH1,    g_H1);
    cudaGetSymbolAddress((void**)&pH2,    g_H2);
    cudaGetSymbolAddress((void**)&pAnch,  g_anch);
    cudaGetSymbolAddress((void**)&pAnchT, g_anchT);
    cudaGetSymbolAddress((void**)&pT1,    g_T1);
    cudaGetSymbolAddress((void**)&pOutp,  g_outproto);

    const int GB = (NN + 63) / 64;   // GEMM row blocks

    // graph preprocessing
    init_kernel  <<<(NN + 255) / 256, 256>>>();
    detect_kernel<<<4, 256>>>((const unsigned*)ei);
    count_kernel <<<(NE + 255) / 256, 256>>>(ei);
    dis_kernel   <<<(NN + 255) / 256, 256>>>();
    scan_kernel  <<<1, 1024>>>();
    fill_kernel  <<<(NE + 255) / 256, 256>>>(ei);

    // layer 0 (aggregate first: agg is linear): H1 = (A_norm x) W0 + b0
    agg_kernel<DIN, false><<<(NN + 7) / 8, 256>>>(x, pM);
    gemm64_kernel<true><<<dim3(GB, DH / 64), 128>>>(pM, W0, b0, pH1, NN, DIN, DH);

    // layer 1: H2 = (A_norm relu(H1)) W1 + b1
    agg_kernel<DH, true><<<(NN + 7) / 8, 256>>>(pH1, pM);
    gemm64_kernel<true><<<dim3(GB, DH / 64), 128>>>(pM, W1, b1, pH2, NN, DH, DH);

    // normalize rows -> hn (in place)
    norm_kernel<<<(NN + 7) / 8, 256>>>(pH2);

    // anchors + prototype head
    gather_kernel<<<(NP * DH + 255) / 256, 256>>>(prot, pH2, pAnch, pAnchT);
    gemm64_kernel<true><<<dim3(NP / 64, DH / 64), 128>>>(pAnch, Wl1, bl1, pT1, NP, DH, DH);
    proto_head_kernel<<<NP, 256>>>(pT1, Wl2, bl2, outpr, pOutp);

    // x_rel = hn @ anchors^T  (cosine sim of unit rows)
    gemm64_kernel<false><<<dim3(GB, NP / 64), 128>>>(pH2, pAnchT, nullptr, xrel, NN, DH, NP);

    // out = log_softmax(x_rel @ out_proto)
    out_kernel<<<(NN + 7) / 8, 256>>>(xrel, pOutp, out);

    (void)out_size; (void)in_sizes; (void)n_in;
}

// round 8
// speedup vs baseline: 2.2793x; 1.4021x over previous
#include <cuda_runtime.h>
#include <cuda_bf16.h>
#include <cstdint>

#define NN  50000
#define NE  800000
#define DIN 128
#define DH  256
#define NP  512
#define NC  16

// ---------------- device scratch (no allocations allowed) ----------------
__device__ float g_deg[NN];
__device__ float g_dis[NN];
__device__ int   g_row_off[NN + 1];
__device__ int   g_fill[NN];
__device__ int   g_csr_src[NE];
__device__ float g_csr_w[NE];
__device__ int   g_bsum[256];
__device__ int   g_boff[256];
__device__ __align__(16) float g_M [(size_t)NN * DH];   // aggregated features
__device__ __align__(16) float g_H1[(size_t)NN * DH];   // layer-0 output (pre-relu)
__device__ __align__(16) float g_H2[(size_t)NN * DH];   // layer-1 output -> normalized
__device__ __align__(16) float g_anch[NP * DH];         // anchors [P][DH] == B[N][K] layout
__device__ __align__(16) float g_Bt [DH * DH];          // transposed weight scratch [N][K]
__device__ __align__(16) float g_T1[NP * DH];           // anchors @ Wl1 + bl1 (pre-relu)
__device__ float g_outproto[NP * NC];
__device__ int   g_not64;

// ---------------- setup kernels ----------------
__global__ void init_kernel() {
    int i = blockIdx.x * blockDim.x + threadIdx.x;
    if (i == 0) g_not64 = 0;
    if (i < NN) g_deg[i] = 1.0f;            // self-loop
}

// int64 vs int32 probe: int64 nonneg values < 2^31 have all-zero high words
__global__ void detect_kernel(const unsigned* __restrict__ ei32) {
    int t = blockIdx.x * blockDim.x + threadIdx.x;
    if (t < 1024) { if (ei32[2 * t + 1] != 0u) atomicOr(&g_not64, 1); }
}

__global__ void count_kernel(const void* __restrict__ ei) {
    int e = blockIdx.x * blockDim.x + threadIdx.x;
    if (e >= NE) return;
    int is64 = (g_not64 == 0);
    int dst = is64 ? (int)((const long long*)ei)[NE + e] : ((const int*)ei)[NE + e];
    atomicAdd(&g_deg[dst], 1.0f);
}

__global__ void dis_kernel() {
    int i = blockIdx.x * blockDim.x + threadIdx.x;
    if (i < NN) g_dis[i] = rsqrtf(g_deg[i]);
}

// ---- decoupled 3-phase scan: per-block sums -> scan sums -> per-block offsets ----
__global__ void blocksum_kernel() {
    __shared__ int sm[8];
    int b = blockIdx.x, tid = threadIdx.x;
    int i = b * 256 + tid;
    int v = (i < NN) ? ((int)g_deg[i]) - 1 : 0;
#pragma unroll
    for (int o = 16; o; o >>= 1) v += __shfl_down_sync(0xffffffffu, v, o);
    if ((tid & 31) == 0) sm[tid >> 5] = v;
    __syncthreads();
    if (tid == 0) {
        int s = 0;
#pragma unroll
        for (int w = 0; w < 8; w++) s += sm[w];
        g_bsum[b] = s;
    }
}

__global__ void bscan_kernel() {
    __shared__ int sm[256];
    int tid = threadIdx.x;
    const int NB = (NN + 255) / 256;
    int v = (tid < NB) ? g_bsum[tid] : 0;
    sm[tid] = v; __syncthreads();
    for (int o = 1; o < 256; o <<= 1) {
        int t = (tid >= o) ? sm[tid - o] : 0;
        __syncthreads(); sm[tid] += t; __syncthreads();
    }
    g_boff[tid] = sm[tid] - v;     // exclusive
}

__global__ void rowoff_kernel() {
    __shared__ int sm[256];
    int b = blockIdx.x, tid = threadIdx.x;
    int i = b * 256 + tid;
    int v = (i < NN) ? ((int)g_deg[i]) - 1 : 0;
    sm[tid] = v; __syncthreads();
    for (int o = 1; o < 256; o <<= 1) {
        int t = (tid >= o) ? sm[tid - o] : 0;
        __syncthreads(); sm[tid] += t; __syncthreads();
    }
    int incl = sm[tid] + g_boff[b];
    if (i < NN) {
        int ex = incl - v;
        g_row_off[i] = ex;
        g_fill[i]    = ex;
        if (i == NN - 1) g_row_off[NN] = incl;
    }
}

__global__ void fill_kernel(const void* __restrict__ ei) {
    int e = blockIdx.x * blockDim.x + threadIdx.x;
    if (e >= NE) return;
    int is64 = (g_not64 == 0);
    int src, dst;
    if (is64) {
        src = (int)((const long long*)ei)[e];
        dst = (int)((const long long*)ei)[NE + e];
    } else {
        src = ((const int*)ei)[e];
        dst = ((const int*)ei)[NE + e];
    }
    int pos = atomicAdd(&g_fill[dst], 1);
    g_csr_src[pos] = src;
    g_csr_w[pos]   = g_dis[src] * g_dis[dst];
}

// ---------------- weight transpose: Bt[n][k] = W[k][n] ----------------
__global__ void transpose_kernel(const float* __restrict__ W, float* __restrict__ Bt,
                                 int K, int N)
{
    int idx = blockIdx.x * blockDim.x + threadIdx.x;
    if (idx >= K * N) return;
    int n = idx / K, k = idx % K;
    Bt[idx] = W[(size_t)k * N + n];
}

// ---------------- HMMA bf16x3 GEMM (mma.sync, arch-generic PTX) ----------------
// C[M,Ntot] = A[M,K] @ Bt[Ntot,K]^T (+bias).
// CTA 256 thr: tile 128x128, warps 2(M)x4(N), warp tile 64x32, K chunks of 32.
// fp32 -> bf16 hi/lo split; 3 passes (hh, hl, lh) via m16n8k16 bf16 MMA.
#define AST 40   // smem row stride in bf16 (padded: conflict-free fragment loads)

__device__ __forceinline__ void mma_bf16(float* d, uint32_t a0, uint32_t a1,
                                         uint32_t a2, uint32_t a3,
                                         uint32_t b0, uint32_t b1) {
    asm volatile(
        "mma.sync.aligned.m16n8k16.row.col.f32.bf16.bf16.f32 "
        "{%0,%1,%2,%3}, {%4,%5,%6,%7}, {%8,%9}, {%0,%1,%2,%3};"
        : "+f"(d[0]), "+f"(d[1]), "+f"(d[2]), "+f"(d[3])
        : "r"(a0), "r"(a1), "r"(a2), "r"(a3), "r"(b0), "r"(b1));
}

__device__ __forceinline__ void cvt_pair(float a, float b, uint32_t& hi, uint32_t& lo) {
    __nv_bfloat162 h = __floats2bfloat162_rn(a, b);
    float2 f = __bfloat1622float2(h);
    __nv_bfloat162 l = __floats2bfloat162_rn(a - f.x, b - f.y);
    hi = *(uint32_t*)&h;
    lo = *(uint32_t*)&l;
}

template<bool BIAS>
__global__ void __launch_bounds__(256)
mma_gemm_kernel(const float* __restrict__ A, const float* __restrict__ Bt,
                const float* __restrict__ bias, float* __restrict__ C,
                int nrows, int K, int Ntot)
{
    __shared__ __nv_bfloat16 Ah[128 * AST], Al[128 * AST];
    __shared__ __nv_bfloat16 Bh[128 * AST], Bl[128 * AST];
    __shared__ float sbias[128];

    const int tid  = threadIdx.x;
    const int warp = tid >> 5, lane = tid & 31;
    const int row0 = blockIdx.x * 128;
    const int n0   = blockIdx.y * 128;
    const int base_m = (warp >> 2) * 64;   // warp M offset in tile
    const int base_n = (warp & 3) * 32;    // warp N offset in tile

    if (BIAS && tid < 128) sbias[tid] = bias[n0 + tid];

    float acc[4][4][4];
#pragma unroll
    for (int mf = 0; mf < 4; mf++)
#pragma unroll
        for (int nf = 0; nf < 4; nf++)
#pragma unroll
            for (int c = 0; c < 4; c++) acc[mf][nf][c] = 0.f;

    const int r  = tid >> 1;            // 0..127: tile row loaded by this thread
    const int kh = (tid & 1) * 16;      // which 16-k half

    for (int kc = 0; kc < K; kc += 32) {
        __syncthreads();   // previous iteration's fragment reads done
        // A tile: 128 rows x 32 k
        {
            int rg = row0 + r; rg = (rg < nrows) ? rg : (nrows - 1);
            const float4* ap = (const float4*)&A[(size_t)rg * K + kc + kh];
#pragma unroll
            for (int i = 0; i < 4; i++) {
                float4 v = ap[i];
                uint32_t h0, l0, h1, l1;
                cvt_pair(v.x, v.y, h0, l0);
                cvt_pair(v.z, v.w, h1, l1);
                int o = r * AST + kh + i * 4;
                *(uint32_t*)&Ah[o] = h0; *(uint32_t*)&Ah[o + 2] = h1;
                *(uint32_t*)&Al[o] = l0; *(uint32_t*)&Al[o + 2] = l1;
            }
        }
        // B tile: 128 n-rows x 32 k (Bt is [N][K])
        {
            const float4* bp = (const float4*)&Bt[(size_t)(n0 + r) * K + kc + kh];
#pragma unroll
            for (int i = 0; i < 4; i++) {
                float4 v = bp[i];
                uint32_t h0, l0, h1, l1;
                cvt_pair(v.x, v.y, h0, l0);
                cvt_pair(v.z, v.w, h1, l1);
                int o = r * AST + kh + i * 4;
                *(uint32_t*)&Bh[o] = h0; *(uint32_t*)&Bh[o + 2] = h1;
                *(uint32_t*)&Bl[o] = l0; *(uint32_t*)&Bl[o + 2] = l1;
            }
        }
        __syncthreads();

#pragma unroll
        for (int kf = 0; kf < 2; kf++) {
            const int ks = kf * 16 + (lane & 3) * 2;
            const int ms = base_m + (lane >> 2);
            const int ns = base_n + (lane >> 2);

            uint32_t ah[4][4], al[4][4], bh[4][2], bl[4][2];
#pragma unroll
            for (int mf = 0; mf < 4; mf++) {
                int mo = (ms + mf * 16) * AST + ks;
                ah[mf][0] = *(uint32_t*)&Ah[mo];
                ah[mf][1] = *(uint32_t*)&Ah[mo + 8 * AST];
                ah[mf][2] = *(uint32_t*)&Ah[mo + 8];
                ah[mf][3] = *(uint32_t*)&Ah[mo + 8 * AST + 8];
                al[mf][0] = *(uint32_t*)&Al[mo];
                al[mf][1] = *(uint32_t*)&Al[mo + 8 * AST];
                al[mf][2] = *(uint32_t*)&Al[mo + 8];
                al[mf][3] = *(uint32_t*)&Al[mo + 8 * AST + 8];
            }
#pragma unroll
            for (int nf = 0; nf < 4; nf++) {
                int no = (ns + nf * 8) * AST + ks;
                bh[nf][0] = *(uint32_t*)&Bh[no];
                bh[nf][1] = *(uint32_t*)&Bh[no + 8];
                bl[nf][0] = *(uint32_t*)&Bl[no];
                bl[nf][1] = *(uint32_t*)&Bl[no + 8];
            }
#pragma unroll
            for (int mf = 0; mf < 4; mf++)
#pragma unroll
                for (int nf = 0; nf < 4; nf++) {
                    mma_bf16(acc[mf][nf], ah[mf][0], ah[mf][1], ah[mf][2], ah[mf][3],
                             bh[nf][0], bh[nf][1]);
                    mma_bf16(acc[mf][nf], al[mf][0], al[mf][1], al[mf][2], al[mf][3],
                             bh[nf][0], bh[nf][1]);
                    mma_bf16(acc[mf][nf], ah[mf][0], ah[mf][1], ah[mf][2], ah[mf][3],
                             bl[nf][0], bl[nf][1]);
                }
        }
    }

    // epilogue
#pragma unroll
    for (int mf = 0; mf < 4; mf++) {
        int m = row0 + base_m + mf * 16 + (lane >> 2);
#pragma unroll
        for (int nf = 0; nf < 4; nf++) {
            int nloc = base_n + nf * 8 + (lane & 3) * 2;
            float bx = 0.f, by = 0.f;
            if (BIAS) { bx = sbias[nloc]; by = sbias[nloc + 1]; }
            float* cp = &C[(size_t)m * Ntot + n0 + nloc];
            if (m < nrows)
                *(float2*)cp = make_float2(acc[mf][nf][0] + bx, acc[mf][nf][1] + by);
            if (m + 8 < nrows)
                *(float2*)(cp + (size_t)8 * Ntot) =
                    make_float2(acc[mf][nf][2] + bx, acc[mf][nf][3] + by);
        }
    }
}

// ---------------- CSR gather-aggregate ----------------
// H[i] = dis[i]^2 * f(M[i]) + sum_e w_e * f(M[src_e]),  f = relu or identity
template<int D, bool RELU>
__global__ void agg_kernel(const float* __restrict__ Msg, float* __restrict__ Hout)
{
    constexpr int V = D / 128;          // float4s per lane (1 or 2)
    int wid = threadIdx.x >> 5, lane = threadIdx.x & 31;
    int i = blockIdx.x * 8 + wid;
    if (i >= NN) return;
    int cb = lane * 4 * V;

    float d  = g_dis[i];
    float sw = d * d;                   // self-loop weight
    float4 acc[V];
    const float4* mr = (const float4*)(Msg + (size_t)i * D + cb);
#pragma unroll
    for (int v = 0; v < V; v++) {
        float4 m = mr[v];
        if (RELU) { m.x = fmaxf(m.x, 0.f); m.y = fmaxf(m.y, 0.f);
                    m.z = fmaxf(m.z, 0.f); m.w = fmaxf(m.w, 0.f); }
        acc[v] = make_float4(sw * m.x, sw * m.y, sw * m.z, sw * m.w);
    }

    int beg = g_row_off[i], end = g_row_off[i + 1];
    for (int j0 = beg; j0 < end; j0 += 32) {
        int jj = j0 + lane;
        int s = 0; float w = 0.f;
        if (jj < end) { s = g_csr_src[jj]; w = g_csr_w[jj]; }
        int cnt = min(32, end - j0);
        for (int t = 0; t < cnt; t++) {
            int   src = __shfl_sync(0xffffffffu, s, t);
            float ww  = __shfl_sync(0xffffffffu, w, t);
            const float4* sr = (const float4*)(Msg + (size_t)src * D + cb);
#pragma unroll
            for (int v = 0; v < V; v++) {
                float4 m = sr[v];
                if (RELU) { m.x = fmaxf(m.x, 0.f); m.y = fmaxf(m.y, 0.f);
                            m.z = fmaxf(m.z, 0.f); m.w = fmaxf(m.w, 0.f); }
                acc[v].x += ww * m.x; acc[v].y += ww * m.y;
                acc[v].z += ww * m.z; acc[v].w += ww * m.w;
            }
        }
    }
    float4* op = (float4*)(Hout + (size_t)i * D + cb);
#pragma unroll
    for (int v = 0; v < V; v++) op[v] = acc[v];
}

// ---------------- L2 row-normalize in place (warp per row) ----------------
__global__ void norm_kernel(float* __restrict__ H) {
    int wid = threadIdx.x >> 5, lane = threadIdx.x & 31;
    int i = blockIdx.x * 8 + wid;
    if (i >= NN) return;
    float4* p = (float4*)(H + (size_t)i * DH + lane * 8);
    float4 v0 = p[0], v1 = p[1];
    float ss = v0.x * v0.x + v0.y * v0.y + v0.z * v0.z + v0.w * v0.w
             + v1.x * v1.x + v1.y * v1.y + v1.z * v1.z + v1.w * v1.w;
#pragma unroll
    for (int off = 16; off; off >>= 1) ss += __shfl_xor_sync(0xffffffffu, ss, off);
    float rinv = rsqrtf(ss);
    v0.x *= rinv; v0.y *= rinv; v0.z *= rinv; v0.w *= rinv;
    v1.x *= rinv; v1.y *= rinv; v1.z *= rinv; v1.w *= rinv;
    p[0] = v0; p[1] = v1;
}

// ---------------- anchor gather (normalized rows) ----------------
__global__ void gather_kernel(const void* __restrict__ prot,
                              const float* __restrict__ H,
                              float* __restrict__ anch)
{
    int idx = blockIdx.x * blockDim.x + threadIdx.x;
    if (idx >= NP * DH) return;
    int p = idx >> 8, k = idx & 255;
    int is64 = (g_not64 == 0);
    long long node = is64 ? ((const long long*)prot)[p]
                          : (long long)((const int*)prot)[p];
    anch[idx] = H[(size_t)node * DH + k];
}

// ---------------- prototype head: log_softmax(relu(T1) @ Wl2 + bl2) ----------------
__global__ void proto_head_kernel(const float* __restrict__ T1,
                                  const float* __restrict__ Wl2,
                                  const float* __restrict__ bl2,
                                  float* __restrict__ out_g,
                                  float* __restrict__ out_s)
{
    __shared__ float sm[8][NC];
    __shared__ float zz[NC];
    int p = blockIdx.x;
    int tid = threadIdx.x;
    float t = fmaxf(T1[p * DH + tid], 0.0f);
    float part[NC];
#pragma unroll
    for (int c = 0; c < NC; c++) part[c] = t * Wl2[tid * NC + c];
#pragma unroll
    for (int off = 16; off; off >>= 1)
#pragma unroll
        for (int c = 0; c < NC; c++)
            part[c] += __shfl_xor_sync(0xffffffffu, part[c], off);
    int wid = tid >> 5, lane = tid & 31;
    if (lane == 0)
#pragma unroll
        for (int c = 0; c < NC; c++) sm[wid][c] = part[c];
    __syncthreads();
    if (tid < NC) {
        float z = bl2[tid];
#pragma unroll
        for (int w = 0; w < 8; w++) z += sm[w][tid];
        zz[tid] = z;
        __syncwarp(0x0000ffffu);
        float m = -1e30f;
#pragma unroll
        for (int c = 0; c < NC; c++) m = fmaxf(m, zz[c]);
        float s = 0.f;
#pragma unroll
        for (int c = 0; c < NC; c++) s += expf(zz[c] - m);
        float val = z - m - logf(s);
        out_g[p * NC + tid] = val;
        out_s[p * NC + tid] = val;
    }
}

// ---------------- out = log_softmax(x_rel @ out_proto), warp per node row ----------------
__global__ void out_kernel(const float* __restrict__ xrel,
                           const float* __restrict__ outproto,
                           float* __restrict__ out)
{
    __shared__ float ops[NP * 17];   // padded stride -> no bank conflicts
    for (int idx = threadIdx.x; idx < NP * NC; idx += blockDim.x) {
        int p = idx >> 4, c = idx & 15;
        ops[p * 17 + c] = outproto[idx];
    }
    __syncthreads();
    int wid = threadIdx.x >> 5, lane = threadIdx.x & 31;
    int i = blockIdx.x * 8 + wid;
    if (i >= NN) return;
    float acc[NC];
#pragma unroll
    for (int c = 0; c < NC; c++) acc[c] = 0.f;
    const float* xr = xrel + (size_t)i * NP;
#pragma unroll
    for (int j = 0; j < NP / 32; j++) {
        int p = lane + j * 32;
        float xv = xr[p];
        const float* o = &ops[p * 17];
#pragma unroll
        for (int c = 0; c < NC; c++) acc[c] += xv * o[c];
    }
#pragma unroll
    for (int off = 16; off; off >>= 1)
#pragma unroll
        for (int c = 0; c < NC; c++)
            acc[c] += __shfl_xor_sync(0xffffffffu, acc[c], off);
    float m = -1e30f;
#pragma unroll
    for (int c = 0; c < NC; c++) m = fmaxf(m, acc[c]);
    float s = 0.f;
#pragma unroll
    for (int c = 0; c < NC; c++) s += expf(acc[c] - m);
    float l = m + logf(s);
    if (lane < NC) out[(size_t)i * NC + lane] = acc[lane] - l;
}

// ---------------- launch ----------------
extern "C" void kernel_launch(void* const* d_in, const int* in_sizes, int n_in,
                              void* d_out, int out_size)
{
    const float* x    = (const float*)d_in[0];
    const void*  ei   = d_in[1];
    const void*  prot = d_in[2];

    // locate W0 by size (epoch scalar may or may not be materialized as an input)
    int wi = 3;
    while (wi < n_in && in_sizes[wi] != DIN * DH) wi++;
    const float* W0  = (const float*)d_in[wi + 0];
    const float* b0  = (const float*)d_in[wi + 1];
    const float* W1  = (const float*)d_in[wi + 2];
    const float* b1  = (const float*)d_in[wi + 3];
    const float* Wl1 = (const float*)d_in[wi + 4];
    const float* bl1 = (const float*)d_in[wi + 5];
    const float* Wl2 = (const float*)d_in[wi + 6];
    const float* bl2 = (const float*)d_in[wi + 7];

    float* out   = (float*)d_out;                              // [NN, NC]
    float* xrel  = out + (size_t)NN * NC;                      // [NN, NP]
    float* outpr = out + (size_t)NN * NC + (size_t)NN * NP;    // [NP, NC]

    float *pM, *pH1, *pH2, *pAnch, *pBt, *pT1, *pOutp;
    cudaGetSymbolAddress((void**)&pM,    g_M);
    cudaGetSymbolAddress((void**)&pH1,   g_H1);
    cudaGetSymbolAddress((void**)&pH2,   g_H2);
    cudaGetSymbolAddress((void**)&pAnch, g_anch);
    cudaGetSymbolAddress((void**)&pBt,   g_Bt);
    cudaGetSymbolAddress((void**)&pT1,   g_T1);
    cudaGetSymbolAddress((void**)&pOutp, g_outproto);

    const int GB = (NN + 127) / 128;   // GEMM row blocks (128 rows per CTA)
    const int NB = (NN + 255) / 256;

    // graph preprocessing
    init_kernel    <<<(NN + 255) / 256, 256>>>();
    detect_kernel  <<<4, 256>>>((const unsigned*)ei);
    count_kernel   <<<(NE + 255) / 256, 256>>>(ei);
    dis_kernel     <<<(NN + 255) / 256, 256>>>();
    blocksum_kernel<<<NB, 256>>>();
    bscan_kernel   <<<1, 256>>>();
    rowoff_kernel  <<<NB, 256>>>();
    fill_kernel    <<<(NE + 255) / 256, 256>>>(ei);

    // layer 0 (aggregate first: agg is linear): H1 = (A_norm x) W0 + b0
    agg_kernel<DIN, false><<<(NN + 7) / 8, 256>>>(x, pM);
    transpose_kernel<<<(DIN * DH + 255) / 256, 256>>>(W0, pBt, DIN, DH);
    mma_gemm_kernel<true><<<dim3(GB, DH / 128), 256>>>(pM, pBt, b0, pH1, NN, DIN, DH);

    // layer 1: H2 = (A_norm relu(H1)) W1 + b1
    agg_kernel<DH, true><<<(NN + 7) / 8, 256>>>(pH1, pM);
    transpose_kernel<<<(DH * DH + 255) / 256, 256>>>(W1, pBt, DH, DH);
    mma_gemm_kernel<true><<<dim3(GB, DH / 128), 256>>>(pM, pBt, b1, pH2, NN, DH, DH);

    // normalize rows -> hn (in place)
    norm_kernel<<<(NN + 7) / 8, 256>>>(pH2);

    // anchors + prototype head (anchors [P][DH] are already B[N][K] layout)
    gather_kernel<<<(NP * DH + 255) / 256, 256>>>(prot, pH2, pAnch);
    transpose_kernel<<<(DH * DH + 255) / 256, 256>>>(Wl1, pBt, DH, DH);
    mma_gemm_kernel<true><<<dim3(NP / 128, DH / 128), 256>>>(pAnch, pBt, bl1, pT1, NP, DH, DH);
    proto_head_kernel<<<NP, 256>>>(pT1, Wl2, bl2, outpr, pOutp);

    // x_rel = hn @ anchors^T  (cosine sim of unit rows)
    mma_gemm_kernel<false><<<dim3(GB, NP / 128), 256>>>(pH2, pAnch, nullptr, xrel, NN, DH, NP);

    // out = log_softmax(x_rel @ out_proto)
    out_kernel<<<(NN + 7) / 8, 256>>>(xrel, pOutp, out);

    (void)out_size; (void)in_sizes; (void)n_in;
}

// round 11
// speedup vs baseline: 2.3954x; 1.0509x over previous
#include <cuda_runtime.h>
#include <cuda_bf16.h>
#include <cstdint>

#define NN  50000
#define NE  800000
#define DIN 128
#define DH  256
#define NP  512
#define NC  16

// ---------------- device scratch (no allocations allowed) ----------------
__device__ float g_deg[NN];
__device__ float g_dis[NN];
__device__ float g_rinv[NN];
__device__ int   g_row_off[NN + 1];
__device__ int   g_fill[NN];
__device__ int   g_csr_src[NE];
__device__ float g_csr_w[NE];
__device__ int   g_bsum[256];
__device__ int   g_boff[256];
__device__ __align__(16) float g_M [(size_t)NN * DH];   // aggregated features
__device__ __align__(16) float g_H1[(size_t)NN * DH];   // layer-0 output (pre-relu)
__device__ __align__(16) float g_H2[(size_t)NN * DH];   // layer-1 output (unnormalized)
__device__ __align__(16) float g_anch[NP * DH];         // anchors (normalized) [P][DH]
__device__ __align__(16) float g_Bt [DH * DH];          // transposed weight scratch [N][K]
__device__ __align__(16) float g_T1[NP * DH];           // anchors @ Wl1 + bl1 (pre-relu)
__device__ float g_outproto[NP * NC];
__device__ int   g_not64;

// ---------------- setup kernels ----------------
__global__ void init_kernel() {
    int i = blockIdx.x * blockDim.x + threadIdx.x;
    if (i == 0) g_not64 = 0;
    if (i < NN) g_deg[i] = 1.0f;            // self-loop
}

// int64 vs int32 probe: int64 nonneg values < 2^31 have all-zero high words
__global__ void detect_kernel(const unsigned* __restrict__ ei32) {
    int t = blockIdx.x * blockDim.x + threadIdx.x;
    if (t < 1024) { if (ei32[2 * t + 1] != 0u) atomicOr(&g_not64, 1); }
}

__global__ void count_kernel(const void* __restrict__ ei) {
    int e = blockIdx.x * blockDim.x + threadIdx.x;
    if (e >= NE) return;
    int is64 = (g_not64 == 0);
    int dst = is64 ? (int)((const long long*)ei)[NE + e] : ((const int*)ei)[NE + e];
    atomicAdd(&g_deg[dst], 1.0f);
}

__global__ void dis_kernel() {
    int i = blockIdx.x * blockDim.x + threadIdx.x;
    if (i < NN) g_dis[i] = rsqrtf(g_deg[i]);
}

// ---- decoupled 3-phase scan: per-block sums -> scan sums -> per-block offsets ----
__global__ void blocksum_kernel() {
    __shared__ int sm[8];
    int b = blockIdx.x, tid = threadIdx.x;
    int i = b * 256 + tid;
    int v = (i < NN) ? ((int)g_deg[i]) - 1 : 0;
#pragma unroll
    for (int o = 16; o; o >>= 1) v += __shfl_down_sync(0xffffffffu, v, o);
    if ((tid & 31) == 0) sm[tid >> 5] = v;
    __syncthreads();
    if (tid == 0) {
        int s = 0;
#pragma unroll
        for (int w = 0; w < 8; w++) s += sm[w];
        g_bsum[b] = s;
    }
}

__global__ void bscan_kernel() {
    __shared__ int sm[256];
    int tid = threadIdx.x;
    const int NB = (NN + 255) / 256;
    int v = (tid < NB) ? g_bsum[tid] : 0;
    sm[tid] = v; __syncthreads();
    for (int o = 1; o < 256; o <<= 1) {
        int t = (tid >= o) ? sm[tid - o] : 0;
        __syncthreads(); sm[tid] += t; __syncthreads();
    }
    g_boff[tid] = sm[tid] - v;     // exclusive
}

__global__ void rowoff_kernel() {
    __shared__ int sm[256];
    int b = blockIdx.x, tid = threadIdx.x;
    int i = b * 256 + tid;
    int v = (i < NN) ? ((int)g_deg[i]) - 1 : 0;
    sm[tid] = v; __syncthreads();
    for (int o = 1; o < 256; o <<= 1) {
        int t = (tid >= o) ? sm[tid - o] : 0;
        __syncthreads(); sm[tid] += t; __syncthreads();
    }
    int incl = sm[tid] + g_boff[b];
    if (i < NN) {
        int ex = incl - v;
        g_row_off[i] = ex;
        g_fill[i]    = ex;
        if (i == NN - 1) g_row_off[NN] = incl;
    }
}

__global__ void fill_kernel(const void* __restrict__ ei) {
    int e = blockIdx.x * blockDim.x + threadIdx.x;
    if (e >= NE) return;
    int is64 = (g_not64 == 0);
    int src, dst;
    if (is64) {
        src = (int)((const long long*)ei)[e];
        dst = (int)((const long long*)ei)[NE + e];
    } else {
        src = ((const int*)ei)[e];
        dst = ((const int*)ei)[NE + e];
    }
    int pos = atomicAdd(&g_fill[dst], 1);
    g_csr_src[pos] = src;
    g_csr_w[pos]   = g_dis[src] * g_dis[dst];
}

// ---------------- weight transpose: Bt[n][k] = W[k][n] ----------------
__global__ void transpose_kernel(const float* __restrict__ W, float* __restrict__ Bt,
                                 int K, int N)
{
    int idx = blockIdx.x * blockDim.x + threadIdx.x;
    if (idx >= K * N) return;
    int n = idx / K, k = idx % K;
    Bt[idx] = W[(size_t)k * N + n];
}

// ---------------- HMMA bf16x3 GEMM with ldmatrix fragments ----------------
// C[M,Ntot] = A[M,K] @ Bt[Ntot,K]^T (+bias) (optionally row-scaled by rinv[m]).
// CTA 256 thr: tile 128x128, warps 2(M)x4(N), warp tile 64x32, K chunks of 32.
// fp32 -> bf16 hi/lo split; 3 passes (hh, lh, hl) via m16n8k16 bf16 MMA.
#define AST 40   // smem row stride in bf16 (80B: 8-row ldmatrix groups conflict-free)

__device__ __forceinline__ void mma_bf16(float* d, const uint32_t* a,
                                         const uint32_t* b) {
    asm volatile(
        "mma.sync.aligned.m16n8k16.row.col.f32.bf16.bf16.f32 "
        "{%0,%1,%2,%3}, {%4,%5,%6,%7}, {%8,%9}, {%0,%1,%2,%3};"
        : "+f"(d[0]), "+f"(d[1]), "+f"(d[2]), "+f"(d[3])
        : "r"(a[0]), "r"(a[1]), "r"(a[2]), "r"(a[3]), "r"(b[0]), "r"(b[1]));
}
#define LDSM_X4(R, addr) \
    asm volatile("ldmatrix.sync.aligned.m8n8.x4.shared.b16 {%0,%1,%2,%3}, [%4];" \
        : "=r"((R)[0]), "=r"((R)[1]), "=r"((R)[2]), "=r"((R)[3]) : "r"(addr))
#define LDSM_X2(R, addr) \
    asm volatile("ldmatrix.sync.aligned.m8n8.x2.shared.b16 {%0,%1}, [%2];" \
        : "=r"((R)[0]), "=r"((R)[1]) : "r"(addr))

__device__ __forceinline__ void cvt_pair(float a, float b, uint32_t& hi, uint32_t& lo) {
    __nv_bfloat162 h = __floats2bfloat162_rn(a, b);
    float2 f = __bfloat1622float2(h);
    __nv_bfloat162 l = __floats2bfloat162_rn(a - f.x, b - f.y);
    hi = *(uint32_t*)&h;
    lo = *(uint32_t*)&l;
}

template<bool BIAS, bool SCALE>
__global__ void __launch_bounds__(256)
mma_gemm_kernel(const float* __restrict__ A, const float* __restrict__ Bt,
                const float* __restrict__ bias, const float* __restrict__ rinv,
                float* __restrict__ C, int nrows, int K, int Ntot)
{
    __shared__ __nv_bfloat16 Ah[128 * AST], Al[128 * AST];
    __shared__ __nv_bfloat16 Bh[128 * AST], Bl[128 * AST];
    __shared__ float sbias[128];

    const int tid  = threadIdx.x;
    const int warp = tid >> 5, lane = tid & 31;
    const int row0 = blockIdx.x * 128;
    const int n0   = blockIdx.y * 128;
    const int base_m = (warp >> 2) * 64;   // warp M offset in tile
    const int base_n = (warp & 3) * 32;    // warp N offset in tile

    if (BIAS && tid < 128) sbias[tid] = bias[n0 + tid];

    const uint32_t ahB = (uint32_t)__cvta_generic_to_shared(Ah);
    const uint32_t alB = (uint32_t)__cvta_generic_to_shared(Al);
    const uint32_t bhB = (uint32_t)__cvta_generic_to_shared(Bh);
    const uint32_t blB = (uint32_t)__cvta_generic_to_shared(Bl);
    // per-lane ldmatrix row addressing
    const int arow = base_m + (lane & 15);
    const int acol = (lane >> 4) * 8;
    const int brow = base_n + (lane & 7);
    const int bcol = (lane & 8) ? 8 : 0;

    float acc[4][4][4];
#pragma unroll
    for (int mf = 0; mf < 4; mf++)
#pragma unroll
        for (int nf = 0; nf < 4; nf++)
#pragma unroll
            for (int c = 0; c < 4; c++) acc[mf][nf][c] = 0.f;

    const int r  = tid >> 1;            // 0..127: tile row loaded by this thread
    const int kh = (tid & 1) * 16;      // which 16-k half

    for (int kc = 0; kc < K; kc += 32) {
        __syncthreads();   // previous iteration's fragment reads done
        // A tile: 128 rows x 32 k
        {
            int rg = row0 + r; rg = (rg < nrows) ? rg : (nrows - 1);
            const float4* ap = (const float4*)&A[(size_t)rg * K + kc + kh];
#pragma unroll
            for (int i = 0; i < 4; i++) {
                float4 v = ap[i];
                uint32_t h0, l0, h1, l1;
                cvt_pair(v.x, v.y, h0, l0);
                cvt_pair(v.z, v.w, h1, l1);
                int o = r * AST + kh + i * 4;
                *(uint2*)&Ah[o] = make_uint2(h0, h1);
                *(uint2*)&Al[o] = make_uint2(l0, l1);
            }
        }
        // B tile: 128 n-rows x 32 k (Bt is [N][K])
        {
            const float4* bp = (const float4*)&Bt[(size_t)(n0 + r) * K + kc + kh];
#pragma unroll
            for (int i = 0; i < 4; i++) {
                float4 v = bp[i];
                uint32_t h0, l0, h1, l1;
                cvt_pair(v.x, v.y, h0, l0);
                cvt_pair(v.z, v.w, h1, l1);
                int o = r * AST + kh + i * 4;
                *(uint2*)&Bh[o] = make_uint2(h0, h1);
                *(uint2*)&Bl[o] = make_uint2(l0, l1);
            }
        }
        __syncthreads();

#pragma unroll
        for (int kf = 0; kf < 2; kf++) {
            uint32_t bh[4][2], bl[4][2];
#pragma unroll
            for (int nf = 0; nf < 4; nf++) {
                uint32_t boff = (uint32_t)(((brow + nf * 8) * AST + kf * 16 + bcol) * 2);
                LDSM_X2(bh[nf], bhB + boff);
                LDSM_X2(bl[nf], blB + boff);
            }
#pragma unroll
            for (int mf = 0; mf < 4; mf++) {
                uint32_t aoff = (uint32_t)(((arow + mf * 16) * AST + kf * 16 + acol) * 2);
                uint32_t ah[4], al[4];
                LDSM_X4(ah, ahB + aoff);
                LDSM_X4(al, alB + aoff);
#pragma unroll
                for (int nf = 0; nf < 4; nf++) {
                    mma_bf16(acc[mf][nf], ah, bh[nf]);
                    mma_bf16(acc[mf][nf], al, bh[nf]);
                    mma_bf16(acc[mf][nf], ah, bl[nf]);
                }
            }
        }
    }

    // epilogue
#pragma unroll
    for (int mf = 0; mf < 4; mf++) {
        int m = row0 + base_m + mf * 16 + (lane >> 2);
        float s0 = 1.f, s8 = 1.f;
        if (SCALE) {
            if (m < nrows)     s0 = rinv[m];
            if (m + 8 < nrows) s8 = rinv[m + 8];
        }
#pragma unroll
        for (int nf = 0; nf < 4; nf++) {
            int nloc = base_n + nf * 8 + (lane & 3) * 2;
            float bx = 0.f, by = 0.f;
            if (BIAS) { bx = sbias[nloc]; by = sbias[nloc + 1]; }
            float* cp = &C[(size_t)m * Ntot + n0 + nloc];
            if (m < nrows)
                *(float2*)cp = make_float2(acc[mf][nf][0] * s0 + bx,
                                           acc[mf][nf][1] * s0 + by);
            if (m + 8 < nrows)
                *(float2*)(cp + (size_t)8 * Ntot) =
                    make_float2(acc[mf][nf][2] * s8 + bx, acc[mf][nf][3] * s8 + by);
        }
    }
}

// ---------------- CSR gather-aggregate ----------------
// H[i] = dis[i]^2 * f(M[i]) + sum_e w_e * f(M[src_e]),  f = relu or identity
template<int D, bool RELU>
__global__ void agg_kernel(const float* __restrict__ Msg, float* __restrict__ Hout)
{
    constexpr int V = D / 128;          // float4s per lane (1 or 2)
    int wid = threadIdx.x >> 5, lane = threadIdx.x & 31;
    int i = blockIdx.x * 8 + wid;
    if (i >= NN) return;
    int cb = lane * 4 * V;

    float d  = g_dis[i];
    float sw = d * d;                   // self-loop weight
    float4 acc[V];
    const float4* mr = (const float4*)(Msg + (size_t)i * D + cb);
#pragma unroll
    for (int v = 0; v < V; v++) {
        float4 m = mr[v];
        if (RELU) { m.x = fmaxf(m.x, 0.f); m.y = fmaxf(m.y, 0.f);
                    m.z = fmaxf(m.z, 0.f); m.w = fmaxf(m.w, 0.f); }
        acc[v] = make_float4(sw * m.x, sw * m.y, sw * m.z, sw * m.w);
    }

    int beg = g_row_off[i], end = g_row_off[i + 1];
    for (int j0 = beg; j0 < end; j0 += 32) {
        int jj = j0 + lane;
        int s = 0; float w = 0.f;
        if (jj < end) { s = g_csr_src[jj]; w = g_csr_w[jj]; }
        int cnt = min(32, end - j0);
        for (int t = 0; t < cnt; t++) {
            int   src = __shfl_sync(0xffffffffu, s, t);
            float ww  = __shfl_sync(0xffffffffu, w, t);
            const float4* sr = (const float4*)(Msg + (size_t)src * D + cb);
#pragma unroll
            for (int v = 0; v < V; v++) {
                float4 m = sr[v];
                if (RELU) { m.x = fmaxf(m.x, 0.f); m.y = fmaxf(m.y, 0.f);
                            m.z = fmaxf(m.z, 0.f); m.w = fmaxf(m.w, 0.f); }
                acc[v].x += ww * m.x; acc[v].y += ww * m.y;
                acc[v].z += ww * m.z; acc[v].w += ww * m.w;
            }
        }
    }
    float4* op = (float4*)(Hout + (size_t)i * D + cb);
#pragma unroll
    for (int v = 0; v < V; v++) op[v] = acc[v];
}

// ---------------- row inverse-norm (warp per row), no write-back of H ----------------
__global__ void rownorm_kernel(const float* __restrict__ H, float* __restrict__ rinv) {
    int wid = threadIdx.x >> 5, lane = threadIdx.x & 31;
    int i = blockIdx.x * 8 + wid;
    if (i >= NN) return;
    const float4* p = (const float4*)(H + (size_t)i * DH + lane * 8);
    float4 v0 = p[0], v1 = p[1];
    float ss = v0.x * v0.x + v0.y * v0.y + v0.z * v0.z + v0.w * v0.w
             + v1.x * v1.x + v1.y * v1.y + v1.z * v1.z + v1.w * v1.w;
#pragma unroll
    for (int off = 16; off; off >>= 1) ss += __shfl_xor_sync(0xffffffffu, ss, off);
    if (lane == 0) rinv[i] = rsqrtf(ss);
}

// ---------------- anchor gather (normalized via rinv) ----------------
__global__ void gather_kernel(const void* __restrict__ prot,
                              const float* __restrict__ H,
                              float* __restrict__ anch)
{
    int idx = blockIdx.x * blockDim.x + threadIdx.x;
    if (idx >= NP * DH) return;
    int p = idx >> 8, k = idx & 255;
    int is64 = (g_not64 == 0);
    long long node = is64 ? ((const long long*)prot)[p]
                          : (long long)((const int*)prot)[p];
    anch[idx] = H[(size_t)node * DH + k] * g_rinv[node];
}

// ---------------- prototype head: log_softmax(relu(T1) @ Wl2 + bl2) ----------------
__global__ void proto_head_kernel(const float* __restrict__ T1,
                                  const float* __restrict__ Wl2,
                                  const float* __restrict__ bl2,
                                  float* __restrict__ out_g,
                                  float* __restrict__ out_s)
{
    __shared__ float sm[8][NC];
    __shared__ float zz[NC];
    int p = blockIdx.x;
    int tid = threadIdx.x;
    float t = fmaxf(T1[p * DH + tid], 0.0f);
    float part[NC];
#pragma unroll
    for (int c = 0; c < NC; c++) part[c] = t * Wl2[tid * NC + c];
#pragma unroll
    for (int off = 16; off; off >>= 1)
#pragma unroll
        for (int c = 0; c < NC; c++)
            part[c] += __shfl_xor_sync(0xffffffffu, part[c], off);
    int wid = tid >> 5, lane = tid & 31;
    if (lane == 0)
#pragma unroll
        for (int c = 0; c < NC; c++) sm[wid][c] = part[c];
    __syncthreads();
    if (tid < NC) {
        float z = bl2[tid];
#pragma unroll
        for (int w = 0; w < 8; w++) z += sm[w][tid];
        zz[tid] = z;
        __syncwarp(0x0000ffffu);
        float m = -1e30f;
#pragma unroll
        for (int c = 0; c < NC; c++) m = fmaxf(m, zz[c]);
        float s = 0.f;
#pragma unroll
        for (int c = 0; c < NC; c++) s += expf(zz[c] - m);
        float val = z - m - logf(s);
        out_g[p * NC + tid] = val;
        out_s[p * NC + tid] = val;
    }
}

// ---------------- out = log_softmax(x_rel @ out_proto), warp per node row ----------------
__global__ void out_kernel(const float* __restrict__ xrel,
                           const float* __restrict__ outproto,
                           float* __restrict__ out)
{
    __shared__ float ops[NP * 17];   // padded stride -> no bank conflicts
    for (int idx = threadIdx.x; idx < NP * NC; idx += blockDim.x) {
        int p = idx >> 4, c = idx & 15;
        ops[p * 17 + c] = outproto[idx];
    }
    __syncthreads();
    int wid = threadIdx.x >> 5, lane = threadIdx.x & 31;
    int i = blockIdx.x * 8 + wid;
    if (i >= NN) return;
    float acc[NC];
#pragma unroll
    for (int c = 0; c < NC; c++) acc[c] = 0.f;
    const float* xr = xrel + (size_t)i * NP;
#pragma unroll
    for (int j = 0; j < NP / 32; j++) {
        int p = lane + j * 32;
        float xv = xr[p];
        const float* o = &ops[p * 17];
#pragma unroll
        for (int c = 0; c < NC; c++) acc[c] += xv * o[c];
    }
#pragma unroll
    for (int off = 16; off; off >>= 1)
#pragma unroll
        for (int c = 0; c < NC; c++)
            acc[c] += __shfl_xor_sync(0xffffffffu, acc[c], off);
    float m = -1e30f;
#pragma unroll
    for (int c = 0; c < NC; c++) m = fmaxf(m, acc[c]);
    float s = 0.f;
#pragma unroll
    for (int c = 0; c < NC; c++) s += expf(acc[c] - m);
    float l = m + logf(s);
    if (lane < NC) out[(size_t)i * NC + lane] = acc[lane] - l;
}

// ---------------- launch ----------------
extern "C" void kernel_launch(void* const* d_in, const int* in_sizes, int n_in,
                              void* d_out, int out_size)
{
    const float* x    = (const float*)d_in[0];
    const void*  ei   = d_in[1];
    const void*  prot = d_in[2];

    // locate W0 by size (epoch scalar may or may not be materialized as an input)
    int wi = 3;
    while (wi < n_in && in_sizes[wi] != DIN * DH) wi++;
    const float* W0  = (const float*)d_in[wi + 0];
    const float* b0  = (const float*)d_in[wi + 1];
    const float* W1  = (const float*)d_in[wi + 2];
    const float* b1  = (const float*)d_in[wi + 3];
    const float* Wl1 = (const float*)d_in[wi + 4];
    const float* bl1 = (const float*)d_in[wi + 5];
    const float* Wl2 = (const float*)d_in[wi + 6];
    const float* bl2 = (const float*)d_in[wi + 7];

    float* out   = (float*)d_out;                              // [NN, NC]
    float* xrel  = out + (size_t)NN * NC;                      // [NN, NP]
    float* outpr = out + (size_t)NN * NC + (size_t)NN * NP;    // [NP, NC]

    float *pM, *pH1, *pH2, *pAnch, *pBt, *pT1, *pOutp, *pRinv;
    cudaGetSymbolAddress((void**)&pM,    g_M);
    cudaGetSymbolAddress((void**)&pH1,   g_H1);
    cudaGetSymbolAddress((void**)&pH2,   g_H2);
    cudaGetSymbolAddress((void**)&pAnch, g_anch);
    cudaGetSymbolAddress((void**)&pBt,   g_Bt);
    cudaGetSymbolAddress((void**)&pT1,   g_T1);
    cudaGetSymbolAddress((void**)&pOutp, g_outproto);
    cudaGetSymbolAddress((void**)&pRinv, g_rinv);

    const int GB = (NN + 127) / 128;   // GEMM row blocks (128 rows per CTA)
    const int NB = (NN + 255) / 256;

    // graph preprocessing
    init_kernel    <<<(NN + 255) / 256, 256>>>();
    detect_kernel  <<<4, 256>>>((const unsigned*)ei);
    count_kernel   <<<(NE + 255) / 256, 256>>>(ei);
    dis_kernel     <<<(NN + 255) / 256, 256>>>();
    blocksum_kernel<<<NB, 256>>>();
    bscan_kernel   <<<1, 256>>>();
    rowoff_kernel  <<<NB, 256>>>();
    fill_kernel    <<<(NE + 255) / 256, 256>>>(ei);

    // layer 0 (aggregate first: agg is linear): H1 = (A_norm x) W0 + b0
    agg_kernel<DIN, false><<<(NN + 7) / 8, 256>>>(x, pM);
    transpose_kernel<<<(DIN * DH + 255) / 256, 256>>>(W0, pBt, DIN, DH);
    mma_gemm_kernel<true, false><<<dim3(GB, DH / 128), 256>>>(pM, pBt, b0, nullptr, pH1, NN, DIN, DH);

    // layer 1: H2 = (A_norm relu(H1)) W1 + b1
    agg_kernel<DH, true><<<(NN + 7) / 8, 256>>>(pH1, pM);
    transpose_kernel<<<(DH * DH + 255) / 256, 256>>>(W1, pBt, DH, DH);
    mma_gemm_kernel<true, false><<<dim3(GB, DH / 128), 256>>>(pM, pBt, b1, nullptr, pH2, NN, DH, DH);

    // row inverse norms (H2 stays unnormalized; scaling folded downstream)
    rownorm_kernel<<<(NN + 7) / 8, 256>>>(pH2, pRinv);

    // anchors (normalized at gather) + prototype head
    gather_kernel<<<(NP * DH + 255) / 256, 256>>>(prot, pH2, pAnch);
    transpose_kernel<<<(DH * DH + 255) / 256, 256>>>(Wl1, pBt, DH, DH);
    mma_gemm_kernel<true, false><<<dim3(NP / 128, DH / 128), 256>>>(pAnch, pBt, bl1, nullptr, pT1, NP, DH, DH);
    proto_head_kernel<<<NP, 256>>>(pT1, Wl2, bl2, outpr, pOutp);

    // x_rel = (H2 @ anch^T) * rinv[m]  (anchors already unit-norm)
    mma_gemm_kernel<false, true><<<dim3(GB, NP / 128), 256>>>(pH2, pAnch, nullptr, pRinv, xrel, NN, DH, NP);

    // out = log_softmax(x_rel @ out_proto)
    out_kernel<<<(NN + 7) / 8, 256>>>(xrel, pOutp, out);

    (void)out_size; (void)in_sizes; (void)n_in;
}

// round 14
// speedup vs baseline: 2.4045x; 1.0038x over previous
#include <cuda_runtime.h>
#include <cuda_bf16.h>
#include <cstdint>

#define NN  50000
#define NE  800000
#define DIN 128
#define DH  256
#define NP  512
#define NC  16

// ---------------- device scratch (no allocations allowed) ----------------
__device__ float g_deg[NN];
__device__ float g_dis[NN];
__device__ float g_rinv[NN];
__device__ int   g_row_off[NN + 1];
__device__ int   g_fill[NN];
__device__ int   g_csr_src[NE];
__device__ float g_csr_w[NE];
__device__ int   g_bsum[256];
__device__ int   g_boff[256];
__device__ __align__(16) float g_M [(size_t)NN * DH];   // aggregated features
__device__ __align__(16) float g_H1[(size_t)NN * DH];   // layer-0 output (pre-relu)
__device__ __align__(16) float g_H2[(size_t)NN * DH];   // layer-1 output (unnormalized)
__device__ __align__(16) float g_anch[NP * DH];         // anchors (normalized) [P][DH]
__device__ __align__(16) float g_Bt [DH * DH];          // transposed weight scratch [N][K]
__device__ __align__(16) float g_T1[NP * DH];           // anchors @ Wl1 + bl1 (pre-relu)
__device__ float g_outproto[NP * NC];
__device__ float g_G[DH * NC];                          // anch^T @ out_proto
__device__ int   g_not64;

// ---------------- setup kernels ----------------
__global__ void init_kernel() {
    int i = blockIdx.x * blockDim.x + threadIdx.x;
    if (i == 0) g_not64 = 0;
    if (i < NN) g_deg[i] = 1.0f;            // self-loop
}

// int64 vs int32 probe: int64 nonneg values < 2^31 have all-zero high words
__global__ void detect_kernel(const unsigned* __restrict__ ei32) {
    int t = blockIdx.x * blockDim.x + threadIdx.x;
    if (t < 1024) { if (ei32[2 * t + 1] != 0u) atomicOr(&g_not64, 1); }
}

__global__ void count_kernel(const void* __restrict__ ei) {
    int e = blockIdx.x * blockDim.x + threadIdx.x;
    if (e >= NE) return;
    int is64 = (g_not64 == 0);
    int dst = is64 ? (int)((const long long*)ei)[NE + e] : ((const int*)ei)[NE + e];
    atomicAdd(&g_deg[dst], 1.0f);
}

__global__ void dis_kernel() {
    int i = blockIdx.x * blockDim.x + threadIdx.x;
    if (i < NN) g_dis[i] = rsqrtf(g_deg[i]);
}

// ---- decoupled 3-phase scan: per-block sums -> scan sums -> per-block offsets ----
__global__ void blocksum_kernel() {
    __shared__ int sm[8];
    int b = blockIdx.x, tid = threadIdx.x;
    int i = b * 256 + tid;
    int v = (i < NN) ? ((int)g_deg[i]) - 1 : 0;
#pragma unroll
    for (int o = 16; o; o >>= 1) v += __shfl_down_sync(0xffffffffu, v, o);
    if ((tid & 31) == 0) sm[tid >> 5] = v;
    __syncthreads();
    if (tid == 0) {
        int s = 0;
#pragma unroll
        for (int w = 0; w < 8; w++) s += sm[w];
        g_bsum[b] = s;
    }
}

__global__ void bscan_kernel() {
    __shared__ int sm[256];
    int tid = threadIdx.x;
    const int NB = (NN + 255) / 256;
    int v = (tid < NB) ? g_bsum[tid] : 0;
    sm[tid] = v; __syncthreads();
    for (int o = 1; o < 256; o <<= 1) {
        int t = (tid >= o) ? sm[tid - o] : 0;
        __syncthreads(); sm[tid] += t; __syncthreads();
    }
    g_boff[tid] = sm[tid] - v;     // exclusive
}

__global__ void rowoff_kernel() {
    __shared__ int sm[256];
    int b = blockIdx.x, tid = threadIdx.x;
    int i = b * 256 + tid;
    int v = (i < NN) ? ((int)g_deg[i]) - 1 : 0;
    sm[tid] = v; __syncthreads();
    for (int o = 1; o < 256; o <<= 1) {
        int t = (tid >= o) ? sm[tid - o] : 0;
        __syncthreads(); sm[tid] += t; __syncthreads();
    }
    int incl = sm[tid] + g_boff[b];
    if (i < NN) {
        int ex = incl - v;
        g_row_off[i] = ex;
        g_fill[i]    = ex;
        if (i == NN - 1) g_row_off[NN] = incl;
    }
}

__global__ void fill_kernel(const void* __restrict__ ei) {
    int e = blockIdx.x * blockDim.x + threadIdx.x;
    if (e >= NE) return;
    int is64 = (g_not64 == 0);
    int src, dst;
    if (is64) {
        src = (int)((const long long*)ei)[e];
        dst = (int)((const long long*)ei)[NE + e];
    } else {
        src = ((const int*)ei)[e];
        dst = ((const int*)ei)[NE + e];
    }
    int pos = atomicAdd(&g_fill[dst], 1);
    g_csr_src[pos] = src;
    g_csr_w[pos]   = g_dis[src] * g_dis[dst];
}

// ---------------- weight transpose: Bt[n][k] = W[k][n] ----------------
__global__ void transpose_kernel(const float* __restrict__ W, float* __restrict__ Bt,
                                 int K, int N)
{
    int idx = blockIdx.x * blockDim.x + threadIdx.x;
    if (idx >= K * N) return;
    int n = idx / K, k = idx % K;
    Bt[idx] = W[(size_t)k * N + n];
}

// ---------------- HMMA bf16x3 GEMM: double-buffered, register-prefetched ----------------
// C[M,Ntot] = A[M,K] @ Bt[Ntot,K]^T (+bias) (optionally row-scaled by rinv[m]).
// CTA 256 thr: tile 128x128, warps 2(M)x4(N), warp tile 64x32, K chunks of 16.
// fp32 -> bf16 hi/lo split; 3 passes (hh, lh, hl) via m16n8k16 bf16 MMA.
#define AST 24                      // smem row stride in bf16 (48B: ldmatrix conflict-free)
#define MATB 6144                   // bytes per matrix tile (128*24*2)
#define MATE 3072                   // bf16 elems per matrix tile
#define BUFB 24576                  // bytes per buffer (4 matrices)
#define SMEM_GEMM (2*BUFB + 512)    // + bias

__device__ __forceinline__ void mma_bf16(float* d, const uint32_t* a,
                                         const uint32_t* b) {
    asm volatile(
        "mma.sync.aligned.m16n8k16.row.col.f32.bf16.bf16.f32 "
        "{%0,%1,%2,%3}, {%4,%5,%6,%7}, {%8,%9}, {%0,%1,%2,%3};"
        : "+f"(d[0]), "+f"(d[1]), "+f"(d[2]), "+f"(d[3])
        : "r"(a[0]), "r"(a[1]), "r"(a[2]), "r"(a[3]), "r"(b[0]), "r"(b[1]));
}
#define LDSM_X4(R, addr) \
    asm volatile("ldmatrix.sync.aligned.m8n8.x4.shared.b16 {%0,%1,%2,%3}, [%4];" \
        : "=r"((R)[0]), "=r"((R)[1]), "=r"((R)[2]), "=r"((R)[3]) : "r"(addr))
#define LDSM_X2(R, addr) \
    asm volatile("ldmatrix.sync.aligned.m8n8.x2.shared.b16 {%0,%1}, [%2];" \
        : "=r"((R)[0]), "=r"((R)[1]) : "r"(addr))

__device__ __forceinline__ void cvt_pair(float a, float b, uint32_t& hi, uint32_t& lo) {
    __nv_bfloat162 h = __floats2bfloat162_rn(a, b);
    float2 f = __bfloat1622float2(h);
    __nv_bfloat162 l = __floats2bfloat162_rn(a - f.x, b - f.y);
    hi = *(uint32_t*)&h;
    lo = *(uint32_t*)&l;
}

template<bool BIAS, bool SCALE>
__global__ void __launch_bounds__(256, 2)
mma_gemm_kernel(const float* __restrict__ A, const float* __restrict__ Bt,
                const float* __restrict__ bias, const float* __restrict__ rinv,
                float* __restrict__ C, int nrows, int K, int Ntot)
{
    extern __shared__ __align__(16) __nv_bfloat16 dsm[];
    float* sbias = (float*)((char*)dsm + 2 * BUFB);

    const int tid  = threadIdx.x;
    const int warp = tid >> 5, lane = tid & 31;
    const int row0 = blockIdx.x * 128;
    const int n0   = blockIdx.y * 128;
    const int base_m = (warp >> 2) * 64;
    const int base_n = (warp & 3) * 32;

    if (BIAS && tid < 128) sbias[tid] = bias[n0 + tid];

    const uint32_t smB = (uint32_t)__cvta_generic_to_shared(dsm);
    const int arow = base_m + (lane & 15);
    const int acol = (lane >> 4) * 8;
    const int brow = base_n + (lane & 7);
    const int bcol = (lane & 8) ? 8 : 0;

    float acc[4][4][4];
#pragma unroll
    for (int mf = 0; mf < 4; mf++)
#pragma unroll
        for (int nf = 0; nf < 4; nf++)
#pragma unroll
            for (int c = 0; c < 4; c++) acc[mf][nf][c] = 0.f;

    // loader: each thread owns row r, k-half kh (8 floats per 16-k chunk)
    const int r  = tid >> 1;
    const int kh = (tid & 1) * 8;
    int rg = row0 + r; rg = (rg < nrows) ? rg : (nrows - 1);
    const float* aRow = &A[(size_t)rg * K + kh];
    const float* bRow = &Bt[(size_t)(n0 + r) * K + kh];

    float4 va0 = *(const float4*)aRow;
    float4 va1 = *(const float4*)(aRow + 4);
    float4 vb0 = *(const float4*)bRow;
    float4 vb1 = *(const float4*)(bRow + 4);

    const int nch = K >> 4;
    const int o = r * AST + kh;
    for (int c = 0; c < nch; c++) {
        __nv_bfloat16* bA = dsm + (c & 1) * (BUFB / 2);   // bf16 units
        {
            uint32_t h0, l0, h1, l1;
            cvt_pair(va0.x, va0.y, h0, l0); cvt_pair(va0.z, va0.w, h1, l1);
            *(uint2*)&bA[o]            = make_uint2(h0, h1);
            *(uint2*)&bA[MATE + o]     = make_uint2(l0, l1);
            cvt_pair(va1.x, va1.y, h0, l0); cvt_pair(va1.z, va1.w, h1, l1);
            *(uint2*)&bA[o + 4]        = make_uint2(h0, h1);
            *(uint2*)&bA[MATE + o + 4] = make_uint2(l0, l1);
            cvt_pair(vb0.x, vb0.y, h0, l0); cvt_pair(vb0.z, vb0.w, h1, l1);
            *(uint2*)&bA[2 * MATE + o]     = make_uint2(h0, h1);
            *(uint2*)&bA[3 * MATE + o]     = make_uint2(l0, l1);
            cvt_pair(vb1.x, vb1.y, h0, l0); cvt_pair(vb1.z, vb1.w, h1, l1);
            *(uint2*)&bA[2 * MATE + o + 4] = make_uint2(h0, h1);
            *(uint2*)&bA[3 * MATE + o + 4] = make_uint2(l0, l1);
        }
        if (c + 1 < nch) {   // prefetch next chunk; completes under the MMA section
            const float* ap = aRow + (c + 1) * 16;
            const float* bp = bRow + (c + 1) * 16;
            va0 = *(const float4*)ap; va1 = *(const float4*)(ap + 4);
            vb0 = *(const float4*)bp; vb1 = *(const float4*)(bp + 4);
        }
        __syncthreads();

        const uint32_t bufb = smB + (uint32_t)((c & 1) * BUFB);
        uint32_t bh[4][2], bl[4][2];
#pragma unroll
        for (int nf = 0; nf < 4; nf++) {
            uint32_t boff = (uint32_t)(((brow + nf * 8) * AST + bcol) * 2);
            LDSM_X2(bh[nf], bufb + 2 * MATB + boff);
            LDSM_X2(bl[nf], bufb + 3 * MATB + boff);
        }
#pragma unroll
        for (int mf = 0; mf < 4; mf++) {
            uint32_t aoff = (uint32_t)(((arow + mf * 16) * AST + acol) * 2);
            uint32_t ah[4], al[4];
            LDSM_X4(ah, bufb + aoff);
            LDSM_X4(al, bufb + MATB + aoff);
#pragma unroll
            for (int nf = 0; nf < 4; nf++) {
                mma_bf16(acc[mf][nf], ah, bh[nf]);
                mma_bf16(acc[mf][nf], al, bh[nf]);
                mma_bf16(acc[mf][nf], ah, bl[nf]);
            }
        }
        // no trailing sync: next iteration writes the other buffer
    }

    // epilogue
#pragma unroll
    for (int mf = 0; mf < 4; mf++) {
        int m = row0 + base_m + mf * 16 + (lane >> 2);
        float s0 = 1.f, s8 = 1.f;
        if (SCALE) {
            if (m < nrows)     s0 = rinv[m];
            if (m + 8 < nrows) s8 = rinv[m + 8];
        }
#pragma unroll
        for (int nf = 0; nf < 4; nf++) {
            int nloc = base_n + nf * 8 + (lane & 3) * 2;
            float bx = 0.f, by = 0.f;
            if (BIAS) { bx = sbias[nloc]; by = sbias[nloc + 1]; }
            float* cp = &C[(size_t)m * Ntot + n0 + nloc];
            if (m < nrows)
                *(float2*)cp = make_float2(acc[mf][nf][0] * s0 + bx,
                                           acc[mf][nf][1] * s0 + by);
            if (m + 8 < nrows)
                *(float2*)(cp + (size_t)8 * Ntot) =
                    make_float2(acc[mf][nf][2] * s8 + bx, acc[mf][nf][3] * s8 + by);
        }
    }
}

// ---------------- CSR gather-aggregate ----------------
// H[i] = dis[i]^2 * f(M[i]) + sum_e w_e * f(M[src_e]),  f = relu or identity
template<int D, bool RELU>
__global__ void agg_kernel(const float* __restrict__ Msg, float* __restrict__ Hout)
{
    constexpr int V = D / 128;          // float4s per lane (1 or 2)
    int wid = threadIdx.x >> 5, lane = threadIdx.x & 31;
    int i = blockIdx.x * 8 + wid;
    if (i >= NN) return;
    int cb = lane * 4 * V;

    float d  = g_dis[i];
    float sw = d * d;                   // self-loop weight
    float4 acc[V];
    const float4* mr = (const float4*)(Msg + (size_t)i * D + cb);
#pragma unroll
    for (int v = 0; v < V; v++) {
        float4 m = mr[v];
        if (RELU) { m.x = fmaxf(m.x, 0.f); m.y = fmaxf(m.y, 0.f);
                    m.z = fmaxf(m.z, 0.f); m.w = fmaxf(m.w, 0.f); }
        acc[v] = make_float4(sw * m.x, sw * m.y, sw * m.z, sw * m.w);
    }

    int beg = g_row_off[i], end = g_row_off[i + 1];
    for (int j0 = beg; j0 < end; j0 += 32) {
        int jj = j0 + lane;
        int s = 0; float w = 0.f;
        if (jj < end) { s = g_csr_src[jj]; w = g_csr_w[jj]; }
        int cnt = min(32, end - j0);
        for (int t = 0; t < cnt; t++) {
            int   src = __shfl_sync(0xffffffffu, s, t);
            float ww  = __shfl_sync(0xffffffffu, w, t);
            const float4* sr = (const float4*)(Msg + (size_t)src * D + cb);
#pragma unroll
            for (int v = 0; v < V; v++) {
                float4 m = sr[v];
                if (RELU) { m.x = fmaxf(m.x, 0.f); m.y = fmaxf(m.y, 0.f);
                            m.z = fmaxf(m.z, 0.f); m.w = fmaxf(m.w, 0.f); }
                acc[v].x += ww * m.x; acc[v].y += ww * m.y;
                acc[v].z += ww * m.z; acc[v].w += ww * m.w;
            }
        }
    }
    float4* op = (float4*)(Hout + (size_t)i * D + cb);
#pragma unroll
    for (int v = 0; v < V; v++) op[v] = acc[v];
}

// ---------------- row inverse-norm (warp per row), no write-back of H ----------------
__global__ void rownorm_kernel(const float* __restrict__ H, float* __restrict__ rinv) {
    int wid = threadIdx.x >> 5, lane = threadIdx.x & 31;
    int i = blockIdx.x * 8 + wid;
    if (i >= NN) return;
    const float4* p = (const float4*)(H + (size_t)i * DH + lane * 8);
    float4 v0 = p[0], v1 = p[1];
    float ss = v0.x * v0.x + v0.y * v0.y + v0.z * v0.z + v0.w * v0.w
             + v1.x * v1.x + v1.y * v1.y + v1.z * v1.z + v1.w * v1.w;
#pragma unroll
    for (int off = 16; off; off >>= 1) ss += __shfl_xor_sync(0xffffffffu, ss, off);
    if (lane == 0) rinv[i] = rsqrtf(ss);
}

// ---------------- anchor gather (normalized via rinv) ----------------
__global__ void gather_kernel(const void* __restrict__ prot,
                              const float* __restrict__ H,
                              float* __restrict__ anch)
{
    int idx = blockIdx.x * blockDim.x + threadIdx.x;
    if (idx >= NP * DH) return;
    int p = idx >> 8, k = idx & 255;
    int is64 = (g_not64 == 0);
    long long node = is64 ? ((const long long*)prot)[p]
                          : (long long)((const int*)prot)[p];
    anch[idx] = H[(size_t)node * DH + k] * g_rinv[node];
}

// ---------------- prototype head: log_softmax(relu(T1) @ Wl2 + bl2) ----------------
__global__ void proto_head_kernel(const float* __restrict__ T1,
                                  const float* __restrict__ Wl2,
                                  const float* __restrict__ bl2,
                                  float* __restrict__ out_g,
                                  float* __restrict__ out_s)
{
    __shared__ float sm[8][NC];
    __shared__ float zz[NC];
    int p = blockIdx.x;
    int tid = threadIdx.x;
    float t = fmaxf(T1[p * DH + tid], 0.0f);
    float part[NC];
#pragma unroll
    for (int c = 0; c < NC; c++) part[c] = t * Wl2[tid * NC + c];
#pragma unroll
    for (int off = 16; off; off >>= 1)
#pragma unroll
        for (int c = 0; c < NC; c++)
            part[c] += __shfl_xor_sync(0xffffffffu, part[c], off);
    int wid = tid >> 5, lane = tid & 31;
    if (lane == 0)
#pragma unroll
        for (int c = 0; c < NC; c++) sm[wid][c] = part[c];
    __syncthreads();
    if (tid < NC) {
        float z = bl2[tid];
#pragma unroll
        for (int w = 0; w < 8; w++) z += sm[w][tid];
        zz[tid] = z;
        __syncwarp(0x0000ffffu);
        float m = -1e30f;
#pragma unroll
        for (int c = 0; c < NC; c++) m = fmaxf(m, zz[c]);
        float s = 0.f;
#pragma unroll
        for (int c = 0; c < NC; c++) s += expf(zz[c] - m);
        float val = z - m - logf(s);
        out_g[p * NC + tid] = val;
        out_s[p * NC + tid] = val;
    }
}

// ---------------- G = anch^T @ out_proto  [DH x NC] ----------------
__global__ void gmat_kernel(const float* __restrict__ anch,
                            const float* __restrict__ proto,
                            float* __restrict__ G)
{
    __shared__ float As[128 * 17];
    __shared__ float Ps[128 * 17];
    int k0 = blockIdx.x * 16;
    int tid = threadIdx.x;
    int kk = tid >> 4, c = tid & 15;
    float acc = 0.f;
    for (int pt = 0; pt < NP / 128; pt++) {
        int p0 = pt * 128;
#pragma unroll
        for (int q = 0; q < 8; q++) {
            int e = tid + q * 256;
            int pr = e >> 4, cc = e & 15;
            As[pr * 17 + cc] = anch[(size_t)(p0 + pr) * DH + k0 + cc];
            Ps[pr * 17 + cc] = proto[(p0 + pr) * NC + cc];
        }
        __syncthreads();
#pragma unroll 8
        for (int p = 0; p < 128; p++)
            acc += As[p * 17 + kk] * Ps[p * 17 + c];
        __syncthreads();
    }
    G[(k0 + kk) * NC + c] = acc;
}

// ---------------- out = log_softmax(rinv * (H2 @ G)), warp per node row ----------------
__global__ void out2_kernel(const float* __restrict__ H2,
                            const float* __restrict__ G,
                            const float* __restrict__ rinv,
                            float* __restrict__ out)
{
    __shared__ float gs[DH * 17];   // padded stride -> conflict-free
    for (int idx = threadIdx.x; idx < DH * NC; idx += blockDim.x) {
        int k = idx >> 4, c = idx & 15;
        gs[k * 17 + c] = G[idx];
    }
    __syncthreads();
    int wid = threadIdx.x >> 5, lane = threadIdx.x & 31;
    int i = blockIdx.x * 8 + wid;
    if (i >= NN) return;
    float acc[NC];
#pragma unroll
    for (int c = 0; c < NC; c++) acc[c] = 0.f;
    const float* hr = H2 + (size_t)i * DH;
#pragma unroll
    for (int j = 0; j < DH / 32; j++) {
        int k = lane + j * 32;
        float hv = hr[k];
        const float* g = &gs[k * 17];
#pragma unroll
        for (int c = 0; c < NC; c++) acc[c] += hv * g[c];
    }
#pragma unroll
    for (int off = 16; off; off >>= 1)
#pragma unroll
        for (int c = 0; c < NC; c++)
            acc[c] += __shfl_xor_sync(0xffffffffu, acc[c], off);
    float ri = rinv[i];
#pragma unroll
    for (int c = 0; c < NC; c++) acc[c] *= ri;
    float m = -1e30f;
#pragma unroll
    for (int c = 0; c < NC; c++) m = fmaxf(m, acc[c]);
    float s = 0.f;
#pragma unroll
    for (int c = 0; c < NC; c++) s += expf(acc[c] - m);
    float l = m + logf(s);
    if (lane < NC) out[(size_t)i * NC + lane] = acc[lane] - l;
}

// ---------------- launch ----------------
extern "C" void kernel_launch(void* const* d_in, const int* in_sizes, int n_in,
                              void* d_out, int out_size)
{
    const float* x    = (const float*)d_in[0];
    const void*  ei   = d_in[1];
    const void*  prot = d_in[2];

    // locate W0 by size (epoch scalar may or may not be materialized as an input)
    int wi = 3;
    while (wi < n_in && in_sizes[wi] != DIN * DH) wi++;
    const float* W0  = (const float*)d_in[wi + 0];
    const float* b0  = (const float*)d_in[wi + 1];
    const float* W1  = (const float*)d_in[wi + 2];
    const float* b1  = (const float*)d_in[wi + 3];
    const float* Wl1 = (const float*)d_in[wi + 4];
    const float* bl1 = (const float*)d_in[wi + 5];
    const float* Wl2 = (const float*)d_in[wi + 6];
    const float* bl2 = (const float*)d_in[wi + 7];

    float* out   = (float*)d_out;                              // [NN, NC]
    float* xrel  = out + (size_t)NN * NC;                      // [NN, NP]
    float* outpr = out + (size_t)NN * NC + (size_t)NN * NP;    // [NP, NC]

    float *pM, *pH1, *pH2, *pAnch, *pBt, *pT1, *pOutp, *pRinv, *pG;
    cudaGetSymbolAddress((void**)&pM,    g_M);
    cudaGetSymbolAddress((void**)&pH1,   g_H1);
    cudaGetSymbolAddress((void**)&pH2,   g_H2);
    cudaGetSymbolAddress((void**)&pAnch, g_anch);
    cudaGetSymbolAddress((void**)&pBt,   g_Bt);
    cudaGetSymbolAddress((void**)&pT1,   g_T1);
    cudaGetSymbolAddress((void**)&pOutp, g_outproto);
    cudaGetSymbolAddress((void**)&pRinv, g_rinv);
    cudaGetSymbolAddress((void**)&pG,    g_G);

    cudaFuncSetAttribute(mma_gemm_kernel<true, false>,
                         cudaFuncAttributeMaxDynamicSharedMemorySize, SMEM_GEMM);
    cudaFuncSetAttribute(mma_gemm_kernel<false, true>,
                         cudaFuncAttributeMaxDynamicSharedMemorySize, SMEM_GEMM);

    const int GB = (NN + 127) / 128;   // GEMM row blocks (128 rows per CTA)
    const int NB = (NN + 255) / 256;

    // graph preprocessing
    init_kernel    <<<(NN + 255) / 256, 256>>>();
    detect_kernel  <<<4, 256>>>((const unsigned*)ei);
    count_kernel   <<<(NE + 255) / 256, 256>>>(ei);
    dis_kernel     <<<(NN + 255) / 256, 256>>>();
    blocksum_kernel<<<NB, 256>>>();
    bscan_kernel   <<<1, 256>>>();
    rowoff_kernel  <<<NB, 256>>>();
    fill_kernel    <<<(NE + 255) / 256, 256>>>(ei);

    // layer 0 (aggregate first: agg is linear): H1 = (A_norm x) W0 + b0
    agg_kernel<DIN, false><<<(NN + 7) / 8, 256>>>(x, pM);
    transpose_kernel<<<(DIN * DH + 255) / 256, 256>>>(W0, pBt, DIN, DH);
    mma_gemm_kernel<true, false><<<dim3(GB, DH / 128), 256, SMEM_GEMM>>>(
        pM, pBt, b0, nullptr, pH1, NN, DIN, DH);

    // layer 1: H2 = (A_norm relu(H1)) W1 + b1
    agg_kernel<DH, true><<<(NN + 7) / 8, 256>>>(pH1, pM);
    transpose_kernel<<<(DH * DH + 255) / 256, 256>>>(W1, pBt, DH, DH);
    mma_gemm_kernel<true, false><<<dim3(GB, DH / 128), 256, SMEM_GEMM>>>(
        pM, pBt, b1, nullptr, pH2, NN, DH, DH);

    // row inverse norms (H2 stays unnormalized; scaling folded downstream)
    rownorm_kernel<<<(NN + 7) / 8, 256>>>(pH2, pRinv);

    // anchors (normalized at gather) + prototype head
    gather_kernel<<<(NP * DH + 255) / 256, 256>>>(prot, pH2, pAnch);
    transpose_kernel<<<(DH * DH + 255) / 256, 256>>>(Wl1, pBt, DH, DH);
    mma_gemm_kernel<true, false><<<dim3(NP / 128, DH / 128), 256, SMEM_GEMM>>>(
        pAnch, pBt, bl1, nullptr, pT1, NP, DH, DH);
    proto_head_kernel<<<NP, 256>>>(pT1, Wl2, bl2, outpr, pOutp);

    // x_rel = (H2 @ anch^T) * rinv[m]  (anchors already unit-norm; xrel is an output)
    mma_gemm_kernel<false, true><<<dim3(GB, NP / 128), 256, SMEM_GEMM>>>(
        pH2, pAnch, nullptr, pRinv, xrel, NN, DH, NP);

    // out = log_softmax(rinv * (H2 @ (anch^T @ out_proto)))
    gmat_kernel<<<DH / 16, 256>>>(pAnch, pOutp, pG);
    out2_kernel<<<(NN + 7) / 8, 256>>>(pH2, pG, pRinv, out);

    (void)out_size; (void)in_sizes; (void)n_in;
}

// round 17
// speedup vs baseline: 2.8189x; 1.1724x over previous
#include <cuda_runtime.h>
#include <cuda_fp16.h>
#include <cstdint>

#define NN  50000
#define NE  800000
#define DIN 128
#define DH  256
#define NP  512
#define NC  16

// ---------------- device scratch (no allocations allowed) ----------------
__device__ float g_deg[NN];
__device__ float g_dis[NN];
__device__ float g_rinv[NN];
__device__ int   g_row_off[NN + 1];
__device__ int   g_fill[NN];
__device__ int   g_csr_src[NE];
__device__ float g_csr_w[NE];
__device__ int   g_bsum[256];
__device__ int   g_boff[256];
__device__ __align__(16) float g_M [(size_t)NN * DH];   // aggregated features
__device__ __align__(16) float g_H1[(size_t)NN * DH];   // layer-0 output (pre-relu)
__device__ __align__(16) float g_H2[(size_t)NN * DH];   // layer-1 output (unnormalized)
__device__ __align__(16) float g_anch[NP * DH];         // anchors (normalized) [P][DH]
__device__ __align__(16) float g_Bt0[DIN * DH];         // W0^T [N][K]
__device__ __align__(16) float g_Bt1[DH * DH];          // W1^T
__device__ __align__(16) float g_Bt2[DH * DH];          // Wl1^T
__device__ __align__(16) float g_T1[NP * DH];           // anchors @ Wl1 + bl1 (pre-relu)
__device__ float g_outproto[NP * NC];
__device__ float g_G[DH * NC];                          // anch^T @ out_proto
__device__ int   g_not64;

// ---------------- setup kernels ----------------
__global__ void init_kernel(const unsigned* __restrict__ ei32) {
    int i = blockIdx.x * blockDim.x + threadIdx.x;
    if (i == 0) g_not64 = 0;
    if (i < NN) g_deg[i] = 1.0f;            // self-loop
    // int64 vs int32 probe: int64 nonneg values < 2^31 have all-zero high words
    if (i < 1024) { if (ei32[2 * i + 1] != 0u) atomicOr(&g_not64, 1); }
}

__global__ void count_kernel(const void* __restrict__ ei) {
    int e = blockIdx.x * blockDim.x + threadIdx.x;
    if (e >= NE) return;
    int is64 = (g_not64 == 0);
    int dst = is64 ? (int)((const long long*)ei)[NE + e] : ((const int*)ei)[NE + e];
    atomicAdd(&g_deg[dst], 1.0f);
}

// dis + per-block degree sums in one pass (both read g_deg)
__global__ void disblock_kernel() {
    __shared__ int sm[8];
    int b = blockIdx.x, tid = threadIdx.x;
    int i = b * 256 + tid;
    float dg = (i < NN) ? g_deg[i] : 1.0f;
    if (i < NN) g_dis[i] = rsqrtf(dg);
    int v = (i < NN) ? ((int)dg) - 1 : 0;
#pragma unroll
    for (int o = 16; o; o >>= 1) v += __shfl_down_sync(0xffffffffu, v, o);
    if ((tid & 31) == 0) sm[tid >> 5] = v;
    __syncthreads();
    if (tid == 0) {
        int s = 0;
#pragma unroll
        for (int w = 0; w < 8; w++) s += sm[w];
        g_bsum[b] = s;
    }
}

__global__ void bscan_kernel() {
    __shared__ int sm[256];
    int tid = threadIdx.x;
    const int NB = (NN + 255) / 256;
    int v = (tid < NB) ? g_bsum[tid] : 0;
    sm[tid] = v; __syncthreads();
    for (int o = 1; o < 256; o <<= 1) {
        int t = (tid >= o) ? sm[tid - o] : 0;
        __syncthreads(); sm[tid] += t; __syncthreads();
    }
    g_boff[tid] = sm[tid] - v;     // exclusive
}

__global__ void rowoff_kernel() {
    __shared__ int sm[256];
    int b = blockIdx.x, tid = threadIdx.x;
    int i = b * 256 + tid;
    int v = (i < NN) ? ((int)g_deg[i]) - 1 : 0;
    sm[tid] = v; __syncthreads();
    for (int o = 1; o < 256; o <<= 1) {
        int t = (tid >= o) ? sm[tid - o] : 0;
        __syncthreads(); sm[tid] += t; __syncthreads();
    }
    int incl = sm[tid] + g_boff[b];
    if (i < NN) {
        int ex = incl - v;
        g_row_off[i] = ex;
        g_fill[i]    = ex;
        if (i == NN - 1) g_row_off[NN] = incl;
    }
}

__global__ void fill_kernel(const void* __restrict__ ei) {
    int e = blockIdx.x * blockDim.x + threadIdx.x;
    if (e >= NE) return;
    int is64 = (g_not64 == 0);
    int src, dst;
    if (is64) {
        src = (int)((const long long*)ei)[e];
        dst = (int)((const long long*)ei)[NE + e];
    } else {
        src = ((const int*)ei)[e];
        dst = ((const int*)ei)[NE + e];
    }
    int pos = atomicAdd(&g_fill[dst], 1);
    g_csr_src[pos] = src;
    g_csr_w[pos]   = g_dis[src] * g_dis[dst];
}

// ---------------- all weight transposes in one launch ----------------
__global__ void transpose_all_kernel(const float* __restrict__ W0,
                                     const float* __restrict__ W1,
                                     const float* __restrict__ Wl1,
                                     float* __restrict__ B0,
                                     float* __restrict__ B1,
                                     float* __restrict__ B2)
{
    int idx = blockIdx.x * blockDim.x + threadIdx.x;
    if (idx < DIN * DH) {
        int n = idx / DIN, k = idx % DIN;
        B0[idx] = W0[(size_t)k * DH + n];
    }
    idx -= DIN * DH;
    if (idx >= 0 && idx < DH * DH) {
        int n = idx / DH, k = idx % DH;
        B1[idx] = W1[(size_t)k * DH + n];
    }
    idx -= DH * DH;
    if (idx >= 0 && idx < DH * DH) {
        int n = idx / DH, k = idx % DH;
        B2[idx] = Wl1[(size_t)k * DH + n];
    }
}

// ---------------- HMMA fp16 2-pass GEMM: double-buffered, register-prefetched ----------------
// C[M,Ntot] = A[M,K] @ Bt[Ntot,K]^T (+bias) (optionally row-scaled by rinv[m]).
// A split into fp16 hi+lo (exact to 2^-22); B fp16-rounded once (2^-11).
// D = a_hi*b_h + a_lo*b_h  -> error = a*(b - b_h) ~ 2^-11 relative.
// CTA 256 thr: tile 128x128, warps 2(M)x4(N), warp tile 64x32, K chunks of 16.
#define AST 24                      // smem row stride in fp16 (48B: ldmatrix conflict-free)
#define MATB 6144                   // bytes per matrix tile (128*24*2)
#define MATE 3072                   // fp16 elems per matrix tile
#define BUFB 18432                  // bytes per buffer (3 matrices: Ah, Al, Bh)
#define SMEM_GEMM (2*BUFB + 512)    // + bias

__device__ __forceinline__ void mma_f16(float* d, const uint32_t* a,
                                        const uint32_t* b) {
    asm volatile(
        "mma.sync.aligned.m16n8k16.row.col.f32.f16.f16.f32 "
        "{%0,%1,%2,%3}, {%4,%5,%6,%7}, {%8,%9}, {%0,%1,%2,%3};"
        : "+f"(d[0]), "+f"(d[1]), "+f"(d[2]), "+f"(d[3])
        : "r"(a[0]), "r"(a[1]), "r"(a[2]), "r"(a[3]), "r"(b[0]), "r"(b[1]));
}
#define LDSM_X4(R, addr) \
    asm volatile("ldmatrix.sync.aligned.m8n8.x4.shared.b16 {%0,%1,%2,%3}, [%4];" \
        : "=r"((R)[0]), "=r"((R)[1]), "=r"((R)[2]), "=r"((R)[3]) : "r"(addr))
#define LDSM_X2(R, addr) \
    asm volatile("ldmatrix.sync.aligned.m8n8.x2.shared.b16 {%0,%1}, [%2];" \
        : "=r"((R)[0]), "=r"((R)[1]) : "r"(addr))

__device__ __forceinline__ void cvt_pair_h(float a, float b, uint32_t& hi, uint32_t& lo) {
    __half2 h = __floats2half2_rn(a, b);
    float2 f = __half22float2(h);
    __half2 l = __floats2half2_rn(a - f.x, b - f.y);
    hi = *(uint32_t*)&h;
    lo = *(uint32_t*)&l;
}
__device__ __forceinline__ uint32_t cvt_h(float a, float b) {
    __half2 h = __floats2half2_rn(a, b);
    return *(uint32_t*)&h;
}

template<bool BIAS, bool SCALE>
__global__ void __launch_bounds__(256, 2)
mma_gemm_kernel(const float* __restrict__ A, const float* __restrict__ Bt,
                const float* __restrict__ bias, const float* __restrict__ rinv,
                float* __restrict__ C, int nrows, int K, int Ntot)
{
    extern __shared__ __align__(16) __half dsm[];
    float* sbias = (float*)((char*)dsm + 2 * BUFB);

    const int tid  = threadIdx.x;
    const int warp = tid >> 5, lane = tid & 31;
    const int row0 = blockIdx.x * 128;
    const int n0   = blockIdx.y * 128;
    const int base_m = (warp >> 2) * 64;
    const int base_n = (warp & 3) * 32;

    if (BIAS && tid < 128) sbias[tid] = bias[n0 + tid];

    const uint32_t smB = (uint32_t)__cvta_generic_to_shared(dsm);
    const int arow = base_m + (lane & 15);
    const int acol = (lane >> 4) * 8;
    const int brow = base_n + (lane & 7);
    const int bcol = (lane & 8) ? 8 : 0;

    float acc[4][4][4];
#pragma unroll
    for (int mf = 0; mf < 4; mf++)
#pragma unroll
        for (int nf = 0; nf < 4; nf++)
#pragma unroll
            for (int c = 0; c < 4; c++) acc[mf][nf][c] = 0.f;

    // loader: each thread owns row r, k-half kh (8 floats per 16-k chunk)
    const int r  = tid >> 1;
    const int kh = (tid & 1) * 8;
    int rg = row0 + r; rg = (rg < nrows) ? rg : (nrows - 1);
    const float* aRow = &A[(size_t)rg * K + kh];
    const float* bRow = &Bt[(size_t)(n0 + r) * K + kh];

    float4 va0 = *(const float4*)aRow;
    float4 va1 = *(const float4*)(aRow + 4);
    float4 vb0 = *(const float4*)bRow;
    float4 vb1 = *(const float4*)(bRow + 4);

    const int nch = K >> 4;
    const int o = r * AST + kh;
    for (int c = 0; c < nch; c++) {
        __half* bA = dsm + (c & 1) * (BUFB / 2);   // fp16 units
        {
            uint32_t h0, l0, h1, l1;
            cvt_pair_h(va0.x, va0.y, h0, l0); cvt_pair_h(va0.z, va0.w, h1, l1);
            *(uint2*)&bA[o]            = make_uint2(h0, h1);
            *(uint2*)&bA[MATE + o]     = make_uint2(l0, l1);
            cvt_pair_h(va1.x, va1.y, h0, l0); cvt_pair_h(va1.z, va1.w, h1, l1);
            *(uint2*)&bA[o + 4]        = make_uint2(h0, h1);
            *(uint2*)&bA[MATE + o + 4] = make_uint2(l0, l1);
            *(uint2*)&bA[2 * MATE + o]     = make_uint2(cvt_h(vb0.x, vb0.y),
                                                        cvt_h(vb0.z, vb0.w));
            *(uint2*)&bA[2 * MATE + o + 4] = make_uint2(cvt_h(vb1.x, vb1.y),
                                                        cvt_h(vb1.z, vb1.w));
        }
        if (c + 1 < nch) {   // prefetch next chunk; completes under the MMA section
            const float* ap = aRow + (c + 1) * 16;
            const float* bp = bRow + (c + 1) * 16;
            va0 = *(const float4*)ap; va1 = *(const float4*)(ap + 4);
            vb0 = *(const float4*)bp; vb1 = *(const float4*)(bp + 4);
        }
        __syncthreads();

        const uint32_t bufb = smB + (uint32_t)((c & 1) * BUFB);
        uint32_t bh[4][2];
#pragma unroll
        for (int nf = 0; nf < 4; nf++) {
            uint32_t boff = (uint32_t)(((brow + nf * 8) * AST + bcol) * 2);
            LDSM_X2(bh[nf], bufb + 2 * MATB + boff);
        }
#pragma unroll
        for (int mf = 0; mf < 4; mf++) {
            uint32_t aoff = (uint32_t)(((arow + mf * 16) * AST + acol) * 2);
            uint32_t ah[4], al[4];
            LDSM_X4(ah, bufb + aoff);
            LDSM_X4(al, bufb + MATB + aoff);
#pragma unroll
            for (int nf = 0; nf < 4; nf++) {
                mma_f16(acc[mf][nf], ah, bh[nf]);
                mma_f16(acc[mf][nf], al, bh[nf]);
            }
        }
        // no trailing sync: next iteration writes the other buffer
    }

    // epilogue
#pragma unroll
    for (int mf = 0; mf < 4; mf++) {
        int m = row0 + base_m + mf * 16 + (lane >> 2);
        float s0 = 1.f, s8 = 1.f;
        if (SCALE) {
            if (m < nrows)     s0 = rinv[m];
            if (m + 8 < nrows) s8 = rinv[m + 8];
        }
#pragma unroll
        for (int nf = 0; nf < 4; nf++) {
            int nloc = base_n + nf * 8 + (lane & 3) * 2;
            float bx = 0.f, by = 0.f;
            if (BIAS) { bx = sbias[nloc]; by = sbias[nloc + 1]; }
            float* cp = &C[(size_t)m * Ntot + n0 + nloc];
            if (m < nrows)
                *(float2*)cp = make_float2(acc[mf][nf][0] * s0 + bx,
                                           acc[mf][nf][1] * s0 + by);
            if (m + 8 < nrows)
                *(float2*)(cp + (size_t)8 * Ntot) =
                    make_float2(acc[mf][nf][2] * s8 + bx, acc[mf][nf][3] * s8 + by);
        }
    }
}

// ---------------- CSR gather-aggregate ----------------
// H[i] = dis[i]^2 * f(M[i]) + sum_e w_e * f(M[src_e]),  f = relu or identity
template<int D, bool RELU>
__global__ void agg_kernel(const float* __restrict__ Msg, float* __restrict__ Hout)
{
    constexpr int V = D / 128;          // float4s per lane (1 or 2)
    int wid = threadIdx.x >> 5, lane = threadIdx.x & 31;
    int i = blockIdx.x * 8 + wid;
    if (i >= NN) return;
    int cb = lane * 4 * V;

    float d  = g_dis[i];
    float sw = d * d;                   // self-loop weight
    float4 acc[V];
    const float4* mr = (const float4*)(Msg + (size_t)i * D + cb);
#pragma unroll
    for (int v = 0; v < V; v++) {
        float4 m = mr[v];
        if (RELU) { m.x = fmaxf(m.x, 0.f); m.y = fmaxf(m.y, 0.f);
                    m.z = fmaxf(m.z, 0.f); m.w = fmaxf(m.w, 0.f); }
        acc[v] = make_float4(sw * m.x, sw * m.y, sw * m.z, sw * m.w);
    }

    int beg = g_row_off[i], end = g_row_off[i + 1];
    for (int j0 = beg; j0 < end; j0 += 32) {
        int jj = j0 + lane;
        int s = 0; float w = 0.f;
        if (jj < end) { s = g_csr_src[jj]; w = g_csr_w[jj]; }
        int cnt = min(32, end - j0);
        for (int t = 0; t < cnt; t++) {
            int   src = __shfl_sync(0xffffffffu, s, t);
            float ww  = __shfl_sync(0xffffffffu, w, t);
            const float4* sr = (const float4*)(Msg + (size_t)src * D + cb);
#pragma unroll
            for (int v = 0; v < V; v++) {
                float4 m = sr[v];
                if (RELU) { m.x = fmaxf(m.x, 0.f); m.y = fmaxf(m.y, 0.f);
                            m.z = fmaxf(m.z, 0.f); m.w = fmaxf(m.w, 0.f); }
                acc[v].x += ww * m.x; acc[v].y += ww * m.y;
                acc[v].z += ww * m.z; acc[v].w += ww * m.w;
            }
        }
    }
    float4* op = (float4*)(Hout + (size_t)i * D + cb);
#pragma unroll
    for (int v = 0; v < V; v++) op[v] = acc[v];
}

// ---------------- row inverse-norm (warp per row), no write-back of H ----------------
__global__ void rownorm_kernel(const float* __restrict__ H, float* __restrict__ rinv) {
    int wid = threadIdx.x >> 5, lane = threadIdx.x & 31;
    int i = blockIdx.x * 8 + wid;
    if (i >= NN) return;
    const float4* p = (const float4*)(H + (size_t)i * DH + lane * 8);
    float4 v0 = p[0], v1 = p[1];
    float ss = v0.x * v0.x + v0.y * v0.y + v0.z * v0.z + v0.w * v0.w
             + v1.x * v1.x + v1.y * v1.y + v1.z * v1.z + v1.w * v1.w;
#pragma unroll
    for (int off = 16; off; off >>= 1) ss += __shfl_xor_sync(0xffffffffu, ss, off);
    if (lane == 0) rinv[i] = rsqrtf(ss);
}

// ---------------- anchor gather (normalized via rinv) ----------------
__global__ void gather_kernel(const void* __restrict__ prot,
                              const float* __restrict__ H,
                              float* __restrict__ anch)
{
    int idx = blockIdx.x * blockDim.x + threadIdx.x;
    if (idx >= NP * DH) return;
    int p = idx >> 8, k = idx & 255;
    int is64 = (g_not64 == 0);
    long long node = is64 ? ((const long long*)prot)[p]
                          : (long long)((const int*)prot)[p];
    anch[idx] = H[(size_t)node * DH + k] * g_rinv[node];
}

// ---------------- prototype head: log_softmax(relu(T1) @ Wl2 + bl2) ----------------
__global__ void proto_head_kernel(const float* __restrict__ T1,
                                  const float* __restrict__ Wl2,
                                  const float* __restrict__ bl2,
                                  float* __restrict__ out_g,
                                  float* __restrict__ out_s)
{
    __shared__ float sm[8][NC];
    __shared__ float zz[NC];
    int p = blockIdx.x;
    int tid = threadIdx.x;
    float t = fmaxf(T1[p * DH + tid], 0.0f);
    float part[NC];
#pragma unroll
    for (int c = 0; c < NC; c++) part[c] = t * Wl2[tid * NC + c];
#pragma unroll
    for (int off = 16; off; off >>= 1)
#pragma unroll
        for (int c = 0; c < NC; c++)
            part[c] += __shfl_xor_sync(0xffffffffu, part[c], off);
    int wid = tid >> 5, lane = tid & 31;
    if (lane == 0)
#pragma unroll
        for (int c = 0; c < NC; c++) sm[wid][c] = part[c];
    __syncthreads();
    if (tid < NC) {
        float z = bl2[tid];
#pragma unroll
        for (int w = 0; w < 8; w++) z += sm[w][tid];
        zz[tid] = z;
        __syncwarp(0x0000ffffu);
        float m = -1e30f;
#pragma unroll
        for (int c = 0; c < NC; c++) m = fmaxf(m, zz[c]);
        float s = 0.f;
#pragma unroll
        for (int c = 0; c < NC; c++) s += expf(zz[c] - m);
        float val = z - m - logf(s);
        out_g[p * NC + tid] = val;
        out_s[p * NC + tid] = val;
    }
}

// ---------------- G = anch^T @ out_proto  [DH x NC] ----------------
__global__ void gmat_kernel(const float* __restrict__ anch,
                            const float* __restrict__ proto,
                            float* __restrict__ G)
{
    __shared__ float As[128 * 17];
    __shared__ float Ps[128 * 17];
    int k0 = blockIdx.x * 16;
    int tid = threadIdx.x;
    int kk = tid >> 4, c = tid & 15;
    float acc = 0.f;
    for (int pt = 0; pt < NP / 128; pt++) {
        int p0 = pt * 128;
#pragma unroll
        for (int q = 0; q < 8; q++) {
            int e = tid + q * 256;
            int pr = e >> 4, cc = e & 15;
            As[pr * 17 + cc] = anch[(size_t)(p0 + pr) * DH + k0 + cc];
            Ps[pr * 17 + cc] = proto[(p0 + pr) * NC + cc];
        }
        __syncthreads();
#pragma unroll 8
        for (int p = 0; p < 128; p++)
            acc += As[p * 17 + kk] * Ps[p * 17 + c];
        __syncthreads();
    }
    G[(k0 + kk) * NC + c] = acc;
}

// ---------------- out = log_softmax(rinv * (H2 @ G)), warp per node row ----------------
__global__ void out2_kernel(const float* __restrict__ H2,
                            const float* __restrict__ G,
                            const float* __restrict__ rinv,
                            float* __restrict__ out)
{
    __shared__ float gs[DH * 17];   // padded stride -> conflict-free
    for (int idx = threadIdx.x; idx < DH * NC; idx += blockDim.x) {
        int k = idx >> 4, c = idx & 15;
        gs[k * 17 + c] = G[idx];
    }
    __syncthreads();
    int wid = threadIdx.x >> 5, lane = threadIdx.x & 31;
    int i = blockIdx.x * 8 + wid;
    if (i >= NN) return;
    float acc[NC];
#pragma unroll
    for (int c = 0; c < NC; c++) acc[c] = 0.f;
    const float* hr = H2 + (size_t)i * DH;
#pragma unroll
    for (int j = 0; j < DH / 32; j++) {
        int k = lane + j * 32;
        float hv = hr[k];
        const float* g = &gs[k * 17];
#pragma unroll
        for (int c = 0; c < NC; c++) acc[c] += hv * g[c];
    }
#pragma unroll
    for (int off = 16; off; off >>= 1)
#pragma unroll
        for (int c = 0; c < NC; c++)
            acc[c] += __shfl_xor_sync(0xffffffffu, acc[c], off);
    float ri = rinv[i];
#pragma unroll
    for (int c = 0; c < NC; c++) acc[c] *= ri;
    float m = -1e30f;
#pragma unroll
    for (int c = 0; c < NC; c++) m = fmaxf(m, acc[c]);
    float s = 0.f;
#pragma unroll
    for (int c = 0; c < NC; c++) s += expf(acc[c] - m);
    float l = m + logf(s);
    if (lane < NC) out[(size_t)i * NC + lane] = acc[lane] - l;
}

// ---------------- launch ----------------
extern "C" void kernel_launch(void* const* d_in, const int* in_sizes, int n_in,
                              void* d_out, int out_size)
{
    const float* x    = (const float*)d_in[0];
    const void*  ei   = d_in[1];
    const void*  prot = d_in[2];

    // locate W0 by size (epoch scalar may or may not be materialized as an input)
    int wi = 3;
    while (wi < n_in && in_sizes[wi] != DIN * DH) wi++;
    const float* W0  = (const float*)d_in[wi + 0];
    const float* b0  = (const float*)d_in[wi + 1];
    const float* W1  = (const float*)d_in[wi + 2];
    const float* b1  = (const float*)d_in[wi + 3];
    const float* Wl1 = (const float*)d_in[wi + 4];
    const float* bl1 = (const float*)d_in[wi + 5];
    const float* Wl2 = (const float*)d_in[wi + 6];
    const float* bl2 = (const float*)d_in[wi + 7];

    float* out   = (float*)d_out;                              // [NN, NC]
    float* xrel  = out + (size_t)NN * NC;                      // [NN, NP]
    float* outpr = out + (size_t)NN * NC + (size_t)NN * NP;    // [NP, NC]

    float *pM, *pH1, *pH2, *pAnch, *pBt0, *pBt1, *pBt2, *pT1, *pOutp, *pRinv, *pG;
    cudaGetSymbolAddress((void**)&pM,    g_M);
    cudaGetSymbolAddress((void**)&pH1,   g_H1);
    cudaGetSymbolAddress((void**)&pH2,   g_H2);
    cudaGetSymbolAddress((void**)&pAnch, g_anch);
    cudaGetSymbolAddress((void**)&pBt0,  g_Bt0);
    cudaGetSymbolAddress((void**)&pBt1,  g_Bt1);
    cudaGetSymbolAddress((void**)&pBt2,  g_Bt2);
    cudaGetSymbolAddress((void**)&pT1,   g_T1);
    cudaGetSymbolAddress((void**)&pOutp, g_outproto);
    cudaGetSymbolAddress((void**)&pRinv, g_rinv);
    cudaGetSymbolAddress((void**)&pG,    g_G);

    cudaFuncSetAttribute(mma_gemm_kernel<true, false>,
                         cudaFuncAttributeMaxDynamicSharedMemorySize, SMEM_GEMM);
    cudaFuncSetAttribute(mma_gemm_kernel<false, true>,
                         cudaFuncAttributeMaxDynamicSharedMemorySize, SMEM_GEMM);

    const int GB = (NN + 127) / 128;   // GEMM row blocks (128 rows per CTA)
    const int NB = (NN + 255) / 256;
    const int TTOT = DIN * DH + 2 * DH * DH;

    // graph preprocessing (+ all weight transposes, independent of it)
    init_kernel     <<<NB, 256>>>((const unsigned*)ei);
    transpose_all_kernel<<<(TTOT + 255) / 256, 256>>>(W0, W1, Wl1, pBt0, pBt1, pBt2);
    count_kernel    <<<(NE + 255) / 256, 256>>>(ei);
    disblock_kernel <<<NB, 256>>>();
    bscan_kernel    <<<1, 256>>>();
    rowoff_kernel   <<<NB, 256>>>();
    fill_kernel     <<<(NE + 255) / 256, 256>>>(ei);

    // layer 0 (aggregate first: agg is linear): H1 = (A_norm x) W0 + b0
    agg_kernel<DIN, false><<<(NN + 7) / 8, 256>>>(x, pM);
    mma_gemm_kernel<true, false><<<dim3(GB, DH / 128), 256, SMEM_GEMM>>>(
        pM, pBt0, b0, nullptr, pH1, NN, DIN, DH);

    // layer 1: H2 = (A_norm relu(H1)) W1 + b1
    agg_kernel<DH, true><<<(NN + 7) / 8, 256>>>(pH1, pM);
    mma_gemm_kernel<true, false><<<dim3(GB, DH / 128), 256, SMEM_GEMM>>>(
        pM, pBt1, b1, nullptr, pH2, NN, DH, DH);

    // row inverse norms (H2 stays unnormalized; scaling folded downstream)
    rownorm_kernel<<<(NN + 7) / 8, 256>>>(pH2, pRinv);

    // anchors (normalized at gather) + prototype head
    gather_kernel<<<(NP * DH + 255) / 256, 256>>>(prot, pH2, pAnch);
    mma_gemm_kernel<true, false><<<dim3(NP / 128, DH / 128), 256, SMEM_GEMM>>>(
        pAnch, pBt2, bl1, nullptr, pT1, NP, DH, DH);
    proto_head_kernel<<<NP, 256>>>(pT1, Wl2, bl2, outpr, pOutp);

    // x_rel = (H2 @ anch^T) * rinv[m]  (anchors already unit-norm; xrel is an output)
    mma_gemm_kernel<false, true><<<dim3(GB, NP / 128), 256, SMEM_GEMM>>>(
        pH2, pAnch, nullptr, pRinv, xrel, NN, DH, NP);

    // out = log_softmax(rinv * (H2 @ (anch^T @ out_proto)))
    gmat_kernel<<<DH / 16, 256>>>(pAnch, pOutp, pG);
    out2_kernel<<<(NN + 7) / 8, 256>>>(pH2, pG, pRinv, out);

    (void)out_size; (void)in_sizes; (void)n_in;
}